// round 1
// baseline (speedup 1.0000x reference)
#include <cuda_runtime.h>
#include <math.h>

#define BB 8
#define NN 2048
#define DD 32

// ---------------- scratch (device globals; no allocations) ----------------
__device__ float g_Exy [(size_t)BB * NN * NN];   // exp(-dist(x,y)/2), row-major [b][l][k]
__device__ float g_ExyT[(size_t)BB * NN * NN];   // transpose [b][k][l]
__device__ float g_Exx [(size_t)BB * NN * NN];
__device__ float g_Eyy [(size_t)BB * NN * NN];
__device__ float g_pot[4][BB * NN];              // 0:f 1:g 2:fx 3:fy
__device__ float g_w  [2][BB * NN];              // 0:wa 1:wb
__device__ float g_c  [4][BB * NN];              // eval contributions

__device__ __forceinline__ float* mat_ptr(int m) {
    switch (m) {
        case 0:  return g_Exy;
        case 1:  return g_ExyT;
        case 2:  return g_Exx;
        default: return g_Eyy;
    }
}

// ---------------- build: E = exp(-||x_l - y_k||^2 / 2) ----------------
// grid (NN/64, NN/64, BB), block 256. Each thread computes a 4x4 micro-tile.
// which: 0 -> write g_Exy and g_ExyT;  1 -> g_Exx;  2 -> g_Eyy
__global__ void build_kernel(const float* __restrict__ X,
                             const float* __restrict__ Y,
                             int which)
{
    __shared__ float sx[64][DD + 1];
    __shared__ float sy[64][DD + 1];
    __shared__ float snx[64], sny[64];

    const int b  = blockIdx.z;
    const int l0 = blockIdx.y * 64;
    const int k0 = blockIdx.x * 64;
    const int tid = threadIdx.x;

    const float* Xb = X + (size_t)b * NN * DD;
    const float* Yb = Y + (size_t)b * NN * DD;

    // cooperative load of the two 64x32 point tiles (coalesced)
    for (int i = tid; i < 64 * DD; i += 256) {
        int r = i >> 5, d = i & 31;
        sx[r][d] = Xb[(size_t)(l0 + r) * DD + d];
        sy[r][d] = Yb[(size_t)(k0 + r) * DD + d];
    }
    __syncthreads();

    if (tid < 64) {
        float s = 0.f;
        #pragma unroll
        for (int d = 0; d < DD; d++) s += sx[tid][d] * sx[tid][d];
        snx[tid] = s;
    } else if (tid < 128) {
        int r = tid - 64;
        float s = 0.f;
        #pragma unroll
        for (int d = 0; d < DD; d++) s += sy[r][d] * sy[r][d];
        sny[r] = s;
    }
    __syncthreads();

    const int tl = (tid >> 4) << 2;   // 0..60
    const int tk = (tid & 15) << 2;   // 0..60

    float acc[4][4];
    #pragma unroll
    for (int i = 0; i < 4; i++)
        #pragma unroll
        for (int j = 0; j < 4; j++) acc[i][j] = 0.f;

    #pragma unroll
    for (int d = 0; d < DD; d++) {
        float xv[4], yv[4];
        #pragma unroll
        for (int i = 0; i < 4; i++) xv[i] = sx[tl + i][d];
        #pragma unroll
        for (int j = 0; j < 4; j++) yv[j] = sy[tk + j][d];
        #pragma unroll
        for (int i = 0; i < 4; i++)
            #pragma unroll
            for (int j = 0; j < 4; j++)
                acc[i][j] = fmaf(xv[i], yv[j], acc[i][j]);
    }

    float ev[4][4];
    #pragma unroll
    for (int i = 0; i < 4; i++) {
        float nx = snx[tl + i];
        #pragma unroll
        for (int j = 0; j < 4; j++) {
            float dist = fmaxf(nx + sny[tk + j] - 2.f * acc[i][j], 0.f);
            ev[i][j] = __expf(-0.5f * dist);
        }
    }

    const size_t base = (size_t)b * NN * NN;
    float* E = (which == 0) ? g_Exy : ((which == 1) ? g_Exx : g_Eyy);

    #pragma unroll
    for (int i = 0; i < 4; i++) {
        float4 v = make_float4(ev[i][0], ev[i][1], ev[i][2], ev[i][3]);
        *(float4*)&E[base + (size_t)(l0 + tl + i) * NN + (k0 + tk)] = v;
    }
    if (which == 0) {
        #pragma unroll
        for (int j = 0; j < 4; j++) {
            float4 v = make_float4(ev[0][j], ev[1][j], ev[2][j], ev[3][j]);
            *(float4*)&g_ExyT[base + (size_t)(k0 + tk + j) * NN + (l0 + tl)] = v;
        }
    }
}

// ---------------- init potentials to zero ----------------
__global__ void init_pots()
{
    int i = blockIdx.x * 256 + threadIdx.x;
    if (i < BB * NN) {
        g_pot[0][i] = 0.f; g_pot[1][i] = 0.f;
        g_pot[2][i] = 0.f; g_pot[3][i] = 0.f;
    }
}

// ---------------- w = measure * exp(pot) ----------------
__global__ void compute_w(int psel, const float* __restrict__ meas, int wsel)
{
    int i = blockIdx.x * 256 + threadIdx.x;
    if (i < BB * NN) g_w[wsel][i] = meas[i] * __expf(g_pot[psel][i]);
}

// ---------------- one c_transform pass with damping update ----------------
// pot[row] <- 0.5 * (pot[row] - log( sum_k E[row,k] * w[k] ))
// grid (NN, BB), block 128
__global__ void lse_iter(int mat, int wsel, int psel)
{
    const int b = blockIdx.y, row = blockIdx.x, tid = threadIdx.x;
    const float4* Er = (const float4*)(mat_ptr(mat) + ((size_t)b * NN + row) * NN);
    const float4* wr = (const float4*)(&g_w[wsel][b * NN]);

    float s = 0.f;
    #pragma unroll 4
    for (int i = tid; i < NN / 4; i += 128) {
        float4 e = Er[i];
        float4 w = wr[i];
        s += e.x * w.x; s += e.y * w.y; s += e.z * w.z; s += e.w * w.w;
    }
    #pragma unroll
    for (int o = 16; o; o >>= 1) s += __shfl_xor_sync(0xffffffffu, s, o);

    __shared__ float red[4];
    if ((tid & 31) == 0) red[tid >> 5] = s;
    __syncthreads();
    if (tid == 0) {
        float tot = (red[0] + red[1]) + (red[2] + red[3]);
        float* p = &g_pot[psel][b * NN + row];
        *p = 0.5f * (*p - logf(tot));
    }
}

// ---------------- evaluation pass: c[row] = weight[row] * (-log sum) ----------------
__global__ void lse_eval(int mat, int wsel, const float* __restrict__ wt, int csel)
{
    const int b = blockIdx.y, row = blockIdx.x, tid = threadIdx.x;
    const float4* Er = (const float4*)(mat_ptr(mat) + ((size_t)b * NN + row) * NN);
    const float4* wr = (const float4*)(&g_w[wsel][b * NN]);

    float s = 0.f;
    #pragma unroll 4
    for (int i = tid; i < NN / 4; i += 128) {
        float4 e = Er[i];
        float4 w = wr[i];
        s += e.x * w.x; s += e.y * w.y; s += e.z * w.z; s += e.w * w.w;
    }
    #pragma unroll
    for (int o = 16; o; o >>= 1) s += __shfl_xor_sync(0xffffffffu, s, o);

    __shared__ float red[4];
    if ((tid & 31) == 0) red[tid >> 5] = s;
    __syncthreads();
    if (tid == 0) {
        float tot = (red[0] + red[1]) + (red[2] + red[3]);
        int idx = b * NN + row;
        g_c[csel][idx] = -wt[idx] * logf(tot);
    }
}

// ---------------- final scalar: mean over batch of (c0 + c1 - c2 - c3) ----------------
__global__ void final_reduce(float* __restrict__ out)
{
    const int tid = threadIdx.x;
    float s = 0.f;
    for (int i = tid; i < BB * NN; i += 1024)
        s += (g_c[0][i] + g_c[1][i]) - (g_c[2][i] + g_c[3][i]);

    #pragma unroll
    for (int o = 16; o; o >>= 1) s += __shfl_xor_sync(0xffffffffu, s, o);
    __shared__ float sm[32];
    if ((tid & 31) == 0) sm[tid >> 5] = s;
    __syncthreads();
    if (tid < 32) {
        float v = sm[tid];
        #pragma unroll
        for (int o = 16; o; o >>= 1) v += __shfl_xor_sync(0xffffffffu, v, o);
        if (tid == 0) out[0] = v / (float)BB;
    }
}

// ---------------- launcher ----------------
extern "C" void kernel_launch(void* const* d_in, const int* in_sizes, int n_in,
                              void* d_out, int out_size)
{
    const float* x = (const float*)d_in[0];
    const float* a = (const float*)d_in[1];
    const float* y = (const float*)d_in[2];
    const float* b = (const float*)d_in[3];
    float* out = (float*)d_out;

    dim3 bg(NN / 64, NN / 64, BB);
    build_kernel<<<bg, 256>>>(x, y, 0);   // Exy + ExyT
    build_kernel<<<bg, 256>>>(x, x, 1);   // Exx
    build_kernel<<<bg, 256>>>(y, y, 2);   // Eyy
    init_pots<<<(BB * NN + 255) / 256, 256>>>();

    dim3 lg(NN, BB);

    // potentials(kxy): fn = c(g, log_b, kxy); gn = c(f, log_a, kyx); damped avg
    for (int it = 0; it < 10; it++) {
        compute_w<<<64, 256>>>(0, a, 0);    // wa = a * exp(f)   (old f)
        compute_w<<<64, 256>>>(1, b, 1);    // wb = b * exp(g)   (old g)
        lse_iter<<<lg, 128>>>(0, 1, 0);     // f <- 0.5(f - log(Exy  @ wb))
        lse_iter<<<lg, 128>>>(1, 0, 1);     // g <- 0.5(g - log(ExyT @ wa))
    }
    // sym_potential(x): fx iterations on kxx
    for (int it = 0; it < 10; it++) {
        compute_w<<<64, 256>>>(2, a, 0);    // wa = a * exp(fx)
        lse_iter<<<lg, 128>>>(2, 0, 2);
    }
    // sym_potential(y): fy iterations on kyy
    for (int it = 0; it < 10; it++) {
        compute_w<<<64, 256>>>(3, b, 1);    // wb = b * exp(fy)
        lse_iter<<<lg, 128>>>(3, 1, 3);
    }

    // final evaluations
    compute_w<<<64, 256>>>(1, b, 1);        // wb = b*exp(g)
    lse_eval<<<lg, 128>>>(0, 1, a, 0);      // c0 = a * c(g, log_b, kxy)
    compute_w<<<64, 256>>>(0, a, 0);        // wa = a*exp(f)
    lse_eval<<<lg, 128>>>(1, 0, b, 1);      // c1 = b * c(f, log_a, kyx)
    compute_w<<<64, 256>>>(2, a, 0);        // wa = a*exp(fx)
    lse_eval<<<lg, 128>>>(2, 0, a, 2);      // c2 = a * c(fx, log_a, kxx)
    compute_w<<<64, 256>>>(3, b, 1);        // wb = b*exp(fy)
    lse_eval<<<lg, 128>>>(3, 1, b, 3);      // c3 = b * c(fy, log_b, kyy)

    final_reduce<<<1, 1024>>>(out);
}

// round 2
// speedup vs baseline: 1.3914x; 1.3914x over previous
#include <cuda_runtime.h>
#include <cuda_fp16.h>
#include <math.h>

#define BB 8
#define NN 2048
#define DD 32

// ---------------- scratch (device globals; no allocations) ----------------
// fp16 shifted Gibbs matrices, 67MB each
__device__ __half g_Exy [(size_t)BB * NN * NN];   // exp((shXY_l - dist(x_l,y_k))/2), [b][l][k]
__device__ __half g_ExyT[(size_t)BB * NN * NN];   // exp((shYX_k - dist(y_k,x_l))/2), [b][k][l]
__device__ __half g_Exx [(size_t)BB * NN * NN];   // exp(-dist/2) (no shift; max=1)
__device__ __half g_Eyy [(size_t)BB * NN * NN];
__device__ float g_shift[2][BB * NN];             // 0: xy row shifts, 1: yx row shifts
__device__ float g_pot[4][BB * NN];               // 0:f 1:g 2:fx 3:fy
__device__ float g_w[2][4][BB * NN];              // [parity][slot] slot 0:wf 1:wg 2:wfx 3:wfy
__device__ float g_c[4][BB * NN];                 // eval contributions

__device__ __forceinline__ __half* mat_ptr(int m) {
    switch (m) {
        case 0:  return g_Exy;
        case 1:  return g_ExyT;
        case 2:  return g_Exx;
        default: return g_Eyy;
    }
}

// ---------------- init: pots = 0, w[parity 0] = measures ----------------
__global__ void init_kernel(const float* __restrict__ a, const float* __restrict__ bm)
{
    int i = blockIdx.x * 256 + threadIdx.x;
    if (i < BB * NN) {
        g_pot[0][i] = 0.f; g_pot[1][i] = 0.f;
        g_pot[2][i] = 0.f; g_pot[3][i] = 0.f;
        float av = a[i], bv = bm[i];
        g_w[0][0][i] = av; g_w[0][1][i] = bv;
        g_w[0][2][i] = av; g_w[0][3][i] = bv;
    }
}

// ---------------- row shifts: min dist to 128 sampled partners, minus margin ----------------
// grid (16, BB, 2), block 128.  z=0: rows of Exy (x vs sampled y). z=1: rows of ExyT (y vs x).
__global__ void shift_kernel(const float* __restrict__ x, const float* __restrict__ y)
{
    const int z = blockIdx.z, b = blockIdx.y;
    const int l = blockIdx.x * 128 + threadIdx.x;
    const float* P = z ? y : x;
    const float* Q = z ? x : y;
    const float* Pb = P + (size_t)b * NN * DD;
    const float* Qb = Q + (size_t)b * NN * DD;

    __shared__ float sq[128][DD + 1];
    for (int i = threadIdx.x; i < 128 * DD; i += 128)
        sq[i >> 5][i & 31] = Qb[i];
    __syncthreads();

    float p[DD];
    #pragma unroll
    for (int d = 0; d < DD; d++) p[d] = Pb[(size_t)l * DD + d];

    float mn = 3.4e38f;
    for (int k = 0; k < 128; k++) {
        float acc = 0.f;
        #pragma unroll
        for (int d = 0; d < DD; d++) {
            float df = p[d] - sq[k][d];
            acc = fmaf(df, df, acc);
        }
        mn = fminf(mn, acc);
    }
    g_shift[z][b * NN + l] = mn - 8.f;   // margin against sample missing the true min
}

// ---------------- build: mat[l,k] = fp16( exp((sh_l - dist(P_l,Q_k))/2) ) ----------------
// grid (16, 16, BB), block 256, 128x128 tile, 8x8 micro-tile per thread.
__global__ void build_kernel(const float* __restrict__ P, const float* __restrict__ Q,
                             int shift_sel, int mat_sel)
{
    __shared__ float sp[128][DD + 1];
    __shared__ float sq[128][DD + 1];
    __shared__ float snp[128], snq[128];

    const int b  = blockIdx.z;
    const int l0 = blockIdx.y * 128;
    const int k0 = blockIdx.x * 128;
    const int tid = threadIdx.x;

    const float* Pb = P + (size_t)b * NN * DD;
    const float* Qb = Q + (size_t)b * NN * DD;

    for (int i = tid; i < 128 * DD; i += 256) {
        int r = i >> 5, d = i & 31;
        sp[r][d] = Pb[(size_t)(l0 + r) * DD + d];
        sq[r][d] = Qb[(size_t)(k0 + r) * DD + d];
    }
    __syncthreads();

    if (tid < 128) {
        float s = 0.f;
        #pragma unroll
        for (int d = 0; d < DD; d++) s = fmaf(sp[tid][d], sp[tid][d], s);
        snp[tid] = s;
    } else {
        int r = tid - 128;
        float s = 0.f;
        #pragma unroll
        for (int d = 0; d < DD; d++) s = fmaf(sq[r][d], sq[r][d], s);
        snq[r] = s;
    }
    __syncthreads();

    const int tr = tid >> 4;       // 0..15  (row lane: rows l0 + tr + 16*i)
    const int tc = tid & 15;       // 0..15  (col lane: cols k0 + tc*8 + j)

    float acc[8][8];
    #pragma unroll
    for (int i = 0; i < 8; i++)
        #pragma unroll
        for (int j = 0; j < 8; j++) acc[i][j] = 0.f;

    #pragma unroll
    for (int d = 0; d < DD; d++) {
        float xv[8], yv[8];
        #pragma unroll
        for (int i = 0; i < 8; i++) xv[i] = sp[tr + 16 * i][d];
        #pragma unroll
        for (int j = 0; j < 8; j++) yv[j] = sq[tc * 8 + j][d];
        #pragma unroll
        for (int i = 0; i < 8; i++)
            #pragma unroll
            for (int j = 0; j < 8; j++)
                acc[i][j] = fmaf(xv[i], yv[j], acc[i][j]);
    }

    __half* M = mat_ptr(mat_sel);
    const size_t base = (size_t)b * NN * NN;

    #pragma unroll
    for (int i = 0; i < 8; i++) {
        const int row = l0 + tr + 16 * i;
        const float nx = snp[tr + 16 * i];
        const float sh = (shift_sel >= 0) ? g_shift[shift_sel][b * NN + row] : 0.f;
        union { uint4 u; __half h[8]; } pack;
        #pragma unroll
        for (int j = 0; j < 8; j++) {
            float dd = fmaxf(nx + snq[tc * 8 + j] - 2.f * acc[i][j], 0.f);
            float e = __expf(0.5f * (sh - dd));
            e = fminf(e, 60000.f);
            pack.h[j] = __float2half_rn(e);
        }
        *(uint4*)&M[base + (size_t)row * NN + (k0 + tc * 8)] = pack.u;
    }
}

// ---------------- shared row-dot: sum_k mat[row,k] * w[k], 128 threads ----------------
__device__ __forceinline__ float block_row_sum(const __half* __restrict__ mrow,
                                               const float* __restrict__ wv)
{
    const int tid = threadIdx.x;
    const uint4*  M = (const uint4*)mrow;   // 256 x (8 halves)
    const float4* W = (const float4*)wv;    // 512 x (4 floats)
    float s = 0.f;
    #pragma unroll
    for (int rep = 0; rep < 2; rep++) {
        const int j = tid + rep * 128;
        uint4 m = M[j];
        float4 w0 = W[2 * j], w1 = W[2 * j + 1];
        float2 e0 = __half22float2(*reinterpret_cast<__half2*>(&m.x));
        float2 e1 = __half22float2(*reinterpret_cast<__half2*>(&m.y));
        float2 e2 = __half22float2(*reinterpret_cast<__half2*>(&m.z));
        float2 e3 = __half22float2(*reinterpret_cast<__half2*>(&m.w));
        s += e0.x * w0.x + e0.y * w0.y + e1.x * w0.z + e1.y * w0.w;
        s += e2.x * w1.x + e2.y * w1.y + e3.x * w1.z + e3.y * w1.w;
    }
    #pragma unroll
    for (int o = 16; o; o >>= 1) s += __shfl_xor_sync(0xffffffffu, s, o);

    __shared__ float red[4];
    if ((tid & 31) == 0) red[tid >> 5] = s;
    __syncthreads();
    return (red[0] + red[1]) + (red[2] + red[3]);
}

// ---------------- xy Sinkhorn iteration (one launch per iter) ----------------
// grid (NN, BB, 2), block 128. z=0: f update via Exy rows & wg. z=1: g update via ExyT rows & wf.
// Reads w[par], writes pot and w[par^1]. Jacobi: both read OLD parity only.
__global__ void lse_xy(const float* __restrict__ a, const float* __restrict__ bm, int par)
{
    const int z = blockIdx.z, b = blockIdx.y, row = blockIdx.x;
    const __half* mat = z ? g_ExyT : g_Exy;
    const float* wi = g_w[par][z ? 0 : 1] + b * NN;
    float tot = block_row_sum(mat + ((size_t)b * NN + row) * NN, wi);
    if (threadIdx.x == 0) {
        const int idx = b * NN + row;
        const float sh = g_shift[z][idx];
        float pn = 0.5f * (g_pot[z][idx] - logf(tot) + 0.5f * sh);
        g_pot[z][idx] = pn;
        const float* meas = z ? bm : a;
        g_w[par ^ 1][z][idx] = meas[idx] * __expf(pn);
    }
}

// ---------------- symmetric iterations (xx and yy in one launch) ----------------
// z=0: fx via Exx & wfx (slot 2). z=1: fy via Eyy & wfy (slot 3). No shifts.
__global__ void lse_sym(const float* __restrict__ a, const float* __restrict__ bm, int par)
{
    const int z = blockIdx.z, b = blockIdx.y, row = blockIdx.x;
    const __half* mat = z ? g_Eyy : g_Exx;
    const float* wi = g_w[par][2 + z] + b * NN;
    float tot = block_row_sum(mat + ((size_t)b * NN + row) * NN, wi);
    if (threadIdx.x == 0) {
        const int idx = b * NN + row;
        float pn = 0.5f * (g_pot[2 + z][idx] - logf(tot));
        g_pot[2 + z][idx] = pn;
        const float* meas = z ? bm : a;
        g_w[par ^ 1][2 + z][idx] = meas[idx] * __expf(pn);
    }
}

// ---------------- final evaluations (all 4 in one launch) ----------------
// z=0: c0 = a * c(g, log b, kxy)   rows of Exy,  w slot 1, shift 0
// z=1: c1 = b * c(f, log a, kyx)   rows of ExyT, w slot 0, shift 1
// z=2: c2 = a * c(fx, log a, kxx)  rows of Exx,  w slot 2
// z=3: c3 = b * c(fy, log b, kyy)  rows of Eyy,  w slot 3
__global__ void eval_kernel(const float* __restrict__ a, const float* __restrict__ bm)
{
    const int z = blockIdx.z, b = blockIdx.y, row = blockIdx.x;
    const __half* mat = mat_ptr(z);
    const int wslot = (z == 0) ? 1 : (z == 1) ? 0 : z;
    const float* wi = g_w[0][wslot] + b * NN;   // 10 iters => final parity 0
    float tot = block_row_sum(mat + ((size_t)b * NN + row) * NN, wi);
    if (threadIdx.x == 0) {
        const int idx = b * NN + row;
        const float sh = (z < 2) ? g_shift[z][idx] : 0.f;
        const float* meas = (z == 0 || z == 2) ? a : bm;
        g_c[z][idx] = meas[idx] * (0.5f * sh - logf(tot));
    }
}

// ---------------- final scalar: mean over batch of (c0 + c1 - c2 - c3) ----------------
__global__ void final_reduce(float* __restrict__ out)
{
    const int tid = threadIdx.x;
    float s = 0.f;
    for (int i = tid; i < BB * NN; i += 1024)
        s += (g_c[0][i] + g_c[1][i]) - (g_c[2][i] + g_c[3][i]);

    #pragma unroll
    for (int o = 16; o; o >>= 1) s += __shfl_xor_sync(0xffffffffu, s, o);
    __shared__ float sm[32];
    if ((tid & 31) == 0) sm[tid >> 5] = s;
    __syncthreads();
    if (tid < 32) {
        float v = sm[tid];
        #pragma unroll
        for (int o = 16; o; o >>= 1) v += __shfl_xor_sync(0xffffffffu, v, o);
        if (tid == 0) out[0] = v / (float)BB;
    }
}

// ---------------- launcher ----------------
extern "C" void kernel_launch(void* const* d_in, const int* in_sizes, int n_in,
                              void* d_out, int out_size)
{
    const float* x  = (const float*)d_in[0];
    const float* a  = (const float*)d_in[1];
    const float* y  = (const float*)d_in[2];
    const float* bm = (const float*)d_in[3];
    float* out = (float*)d_out;

    init_kernel<<<(BB * NN + 255) / 256, 256>>>(a, bm);
    shift_kernel<<<dim3(16, BB, 2), 128>>>(x, y);

    dim3 bg(16, 16, BB);
    build_kernel<<<bg, 256>>>(x, y,  0, 0);   // Exy'  (row-shifted)
    build_kernel<<<bg, 256>>>(y, x,  1, 1);   // ExyT' (row-shifted = col shifts of Exy)
    build_kernel<<<bg, 256>>>(x, x, -1, 2);   // Exx
    build_kernel<<<bg, 256>>>(y, y, -1, 3);   // Eyy

    dim3 lg(NN, BB, 2);
    for (int it = 0; it < 10; it++)
        lse_xy<<<lg, 128>>>(a, bm, it & 1);
    for (int it = 0; it < 10; it++)
        lse_sym<<<lg, 128>>>(a, bm, it & 1);

    eval_kernel<<<dim3(NN, BB, 4), 128>>>(a, bm);
    final_reduce<<<1, 1024>>>(out);
}

// round 5
// speedup vs baseline: 1.7529x; 1.2598x over previous
#include <cuda_runtime.h>
#include <cuda_fp16.h>
#include <cuda_bf16.h>
#include <math.h>

#define BB 8
#define NN 2048
#define DD 32
#define RBS 32                      // rows per xy_main block
#define NRB (NN / RBS)              // 64 row-blocks

// ---------------- scratch (device globals; no allocations) ----------------
// NOTE: device symbols are ONLY dereferenced inside kernels (never passed from host).
__device__ __nv_bfloat16 g_Exy[(size_t)BB * NN * NN]; // exp((sh_l - dist(x_l,y_k))/2), bf16
__device__ __half g_Exx[(size_t)BB * NN * NN];        // exp(-dist/2), fp16 (diag=1 dominates rows)
__device__ __half g_Eyy[(size_t)BB * NN * NN];
__device__ float g_shift[BB * NN];               // xy row shifts (x side)
__device__ float g_pot[4][BB * NN];              // 0:f 1:g 2:fx 3:fy
__device__ float g_wg[BB * NN];                  // b * exp(g)
__device__ float g_wap[2][BB * NN];              // a * exp(f - sh/2), parity buffered
__device__ float g_wsym[2][2][BB * NN];          // [parity][0:xx,1:yy]
__device__ float g_colpart[NRB][BB][NN];         // column partial sums
__device__ float g_c[4][BB * NN];                // eval contributions

// ---------------- row shifts: sampled min dist over first 128 y's ----------------
__global__ void shift_kernel(const float* __restrict__ x, const float* __restrict__ y)
{
    const int b = blockIdx.y;
    const int l = blockIdx.x * 128 + threadIdx.x;
    const float* Pb = x + (size_t)b * NN * DD;
    const float* Qb = y + (size_t)b * NN * DD;

    __shared__ float sq[128][DD + 1];
    for (int i = threadIdx.x; i < 128 * DD; i += 128)
        sq[i >> 5][i & 31] = Qb[i];
    __syncthreads();

    float p[DD];
    #pragma unroll
    for (int d = 0; d < DD; d++) p[d] = Pb[(size_t)l * DD + d];

    float mn = 3.4e38f;
    for (int k = 0; k < 128; k++) {
        float acc = 0.f;
        #pragma unroll
        for (int d = 0; d < DD; d++) {
            float df = p[d] - sq[k][d];
            acc = fmaf(df, df, acc);
        }
        mn = fminf(mn, acc);
    }
    g_shift[b * NN + l] = mn;   // bf16 storage: no over/underflow risk either direction
}

// ---------------- init: pots=0, wg=b, wap[0]=a*exp(-sh/2), wsym=measures ----------------
__global__ void init_kernel(const float* __restrict__ a, const float* __restrict__ bm)
{
    int i = blockIdx.x * 256 + threadIdx.x;
    if (i < BB * NN) {
        g_pot[0][i] = 0.f; g_pot[1][i] = 0.f;
        g_pot[2][i] = 0.f; g_pot[3][i] = 0.f;
        g_wg[i] = bm[i];
        g_wap[0][i] = a[i] * __expf(-0.5f * g_shift[i]);
        g_wsym[0][0][i] = a[i];
        g_wsym[0][1][i] = bm[i];
    }
}

// ---------------- shared GEMM-tile core for the builds ----------------
// Computes acc[8][8] = x-tile . y-tile^T plus norms; caller converts+stores.
// block 256, 128x128 tile, 8x8 micro-tile, float2 d-pairs.
struct BuildTile {
    float acc[8][8];
    float nx[8];       // row norms for this thread's 8 rows
    float ny[8];       // col norms for this thread's 8 cols
    int   rows[8];
    int   cols[8];
};

__device__ __forceinline__ void build_tile(const float* __restrict__ P,
                                           const float* __restrict__ Q,
                                           int b, int l0, int k0, BuildTile& T)
{
    __shared__ float sp[128][DD + 2];
    __shared__ float sq[128][DD + 2];
    __shared__ float snp[128], snq[128];

    const int tid = threadIdx.x;
    const float* Pb = P + (size_t)b * NN * DD;
    const float* Qb = Q + (size_t)b * NN * DD;

    for (int i = tid; i < 128 * DD; i += 256) {
        int r = i >> 5, d = i & 31;
        sp[r][d] = Pb[(size_t)(l0 + r) * DD + d];
        sq[r][d] = Qb[(size_t)(k0 + r) * DD + d];
    }
    __syncthreads();

    if (tid < 128) {
        float s = 0.f;
        #pragma unroll
        for (int d = 0; d < DD; d++) s = fmaf(sp[tid][d], sp[tid][d], s);
        snp[tid] = s;
    } else {
        int r = tid - 128;
        float s = 0.f;
        #pragma unroll
        for (int d = 0; d < DD; d++) s = fmaf(sq[r][d], sq[r][d], s);
        snq[r] = s;
    }
    __syncthreads();

    const int tr = tid >> 4;       // 0..15, rows l0 + tr + 16*i
    const int tc = tid & 15;       // 0..15, cols k0 + tc*8 + j

    #pragma unroll
    for (int i = 0; i < 8; i++)
        #pragma unroll
        for (int j = 0; j < 8; j++) T.acc[i][j] = 0.f;

    #pragma unroll 4
    for (int d2 = 0; d2 < DD / 2; d2++) {
        float2 xv[8], yv[8];
        #pragma unroll
        for (int i = 0; i < 8; i++) xv[i] = *(const float2*)&sp[tr + 16 * i][2 * d2];
        #pragma unroll
        for (int j = 0; j < 8; j++) yv[j] = *(const float2*)&sq[tc * 8 + j][2 * d2];
        #pragma unroll
        for (int i = 0; i < 8; i++)
            #pragma unroll
            for (int j = 0; j < 8; j++) {
                T.acc[i][j] = fmaf(xv[i].x, yv[j].x, T.acc[i][j]);
                T.acc[i][j] = fmaf(xv[i].y, yv[j].y, T.acc[i][j]);
            }
    }

    #pragma unroll
    for (int i = 0; i < 8; i++) { T.rows[i] = l0 + tr + 16 * i; T.nx[i] = snp[tr + 16 * i]; }
    #pragma unroll
    for (int j = 0; j < 8; j++) { T.cols[j] = k0 + tc * 8 + j;  T.ny[j] = snq[tc * 8 + j]; }
}

// ---------------- build Exy (bf16, row-shifted) ----------------
__global__ void build_xy(const float* __restrict__ x, const float* __restrict__ y)
{
    const int b = blockIdx.z;
    BuildTile T;
    build_tile(x, y, b, blockIdx.y * 128, blockIdx.x * 128, T);

    const size_t base = (size_t)b * NN * NN;
    #pragma unroll
    for (int i = 0; i < 8; i++) {
        const float sh = g_shift[b * NN + T.rows[i]];
        union { uint4 u; __nv_bfloat16 h[8]; } pack;
        #pragma unroll
        for (int j = 0; j < 8; j++) {
            float dd = fmaxf(T.nx[i] + T.ny[j] - 2.f * T.acc[i][j], 0.f);
            pack.h[j] = __float2bfloat16(__expf(0.5f * (sh - dd)));
        }
        *(uint4*)&g_Exy[base + (size_t)T.rows[i] * NN + T.cols[0]] = pack.u;
    }
}

// ---------------- build Exx / Eyy (fp16, no shift); sel 0:xx 1:yy ----------------
__global__ void build_sym(const float* __restrict__ P, int sel)
{
    const int b = blockIdx.z;
    BuildTile T;
    build_tile(P, P, b, blockIdx.y * 128, blockIdx.x * 128, T);

    __half* M = sel ? g_Eyy : g_Exx;
    const size_t base = (size_t)b * NN * NN;
    #pragma unroll
    for (int i = 0; i < 8; i++) {
        union { uint4 u; __half h[8]; } pack;
        #pragma unroll
        for (int j = 0; j < 8; j++) {
            float dd = fmaxf(T.nx[i] + T.ny[j] - 2.f * T.acc[i][j], 0.f);
            pack.h[j] = __float2half_rn(__expf(-0.5f * dd));
        }
        *(uint4*)&M[base + (size_t)T.rows[i] * NN + T.cols[0]] = pack.u;
    }
}

// ---------------- xy main pass: row sums (f side) + column partials (g side) ----------------
// grid (NRB, BB), block 256 = 8 warps; warp w covers cols [w*256, w*256+256)
// mode 0: Sinkhorn iter (update f, write wap[par^1], emit colparts with wap[par])
// mode 1: eval (write c0, emit colparts with wap[par] = final wa')
__global__ void xy_main(const float* __restrict__ a, int par, int mode)
{
    const int b = blockIdx.y, rb = blockIdx.x;
    const int tid = threadIdx.x, warp = tid >> 5, lane = tid & 31;
    const int c0 = warp * 256 + lane * 8;

    __shared__ float swap_s[RBS];
    __shared__ float rowpart[RBS][9];

    if (tid < RBS) swap_s[tid] = g_wap[par][b * NN + rb * RBS + tid];

    float4 wg0 = *(const float4*)&g_wg[b * NN + c0];
    float4 wg1 = *(const float4*)&g_wg[b * NN + c0 + 4];
    __syncthreads();

    const __nv_bfloat16* Srow = g_Exy + ((size_t)b * NN + rb * RBS) * NN + c0;

    float colacc[8];
    #pragma unroll
    for (int j = 0; j < 8; j++) colacc[j] = 0.f;

    #pragma unroll 2
    for (int g4 = 0; g4 < RBS / 4; g4++) {
        float rd[4];
        #pragma unroll
        for (int rr = 0; rr < 4; rr++) {
            const int r = g4 * 4 + rr;
            uint4 m = *(const uint4*)(Srow + (size_t)r * NN);
            float2 e0 = __bfloat1622float2(*reinterpret_cast<__nv_bfloat162*>(&m.x));
            float2 e1 = __bfloat1622float2(*reinterpret_cast<__nv_bfloat162*>(&m.y));
            float2 e2 = __bfloat1622float2(*reinterpret_cast<__nv_bfloat162*>(&m.z));
            float2 e3 = __bfloat1622float2(*reinterpret_cast<__nv_bfloat162*>(&m.w));
            float wr = swap_s[r];
            float s = 0.f;
            s = fmaf(e0.x, wg0.x, s); s = fmaf(e0.y, wg0.y, s);
            s = fmaf(e1.x, wg0.z, s); s = fmaf(e1.y, wg0.w, s);
            s = fmaf(e2.x, wg1.x, s); s = fmaf(e2.y, wg1.y, s);
            s = fmaf(e3.x, wg1.z, s); s = fmaf(e3.y, wg1.w, s);
            rd[rr] = s;
            colacc[0] = fmaf(e0.x, wr, colacc[0]); colacc[1] = fmaf(e0.y, wr, colacc[1]);
            colacc[2] = fmaf(e1.x, wr, colacc[2]); colacc[3] = fmaf(e1.y, wr, colacc[3]);
            colacc[4] = fmaf(e2.x, wr, colacc[4]); colacc[5] = fmaf(e2.y, wr, colacc[5]);
            colacc[6] = fmaf(e3.x, wr, colacc[6]); colacc[7] = fmaf(e3.y, wr, colacc[7]);
        }
        #pragma unroll
        for (int o = 16; o; o >>= 1) {
            #pragma unroll
            for (int rr = 0; rr < 4; rr++)
                rd[rr] += __shfl_xor_sync(0xffffffffu, rd[rr], o);
        }
        if (lane == 0) {
            #pragma unroll
            for (int rr = 0; rr < 4; rr++) rowpart[g4 * 4 + rr][warp] = rd[rr];
        }
    }

    float* cp = &g_colpart[rb][b][c0];
    *(float4*)cp       = make_float4(colacc[0], colacc[1], colacc[2], colacc[3]);
    *(float4*)(cp + 4) = make_float4(colacc[4], colacc[5], colacc[6], colacc[7]);

    __syncthreads();

    if (tid < RBS) {
        const int row = rb * RBS + tid;
        const int idx = b * NN + row;
        float tot = 0.f;
        #pragma unroll
        for (int w = 0; w < 8; w++) tot += rowpart[tid][w];
        const float sh = g_shift[idx];
        if (mode == 0) {
            float fn = 0.5f * (g_pot[0][idx] - logf(tot) + 0.5f * sh);
            g_pot[0][idx] = fn;
            g_wap[par ^ 1][idx] = a[idx] * __expf(fn - 0.5f * sh);
        } else {
            g_c[0][idx] = a[idx] * (0.5f * sh - logf(tot));
        }
    }
}

// ---------------- xy finalize: reduce column partials, update g / emit c1 ----------------
__global__ void xy_fin(const float* __restrict__ bm, int mode)
{
    const int i = blockIdx.x * 256 + threadIdx.x;       // i = b*NN + k
    const int b = i >> 11, k = i & (NN - 1);
    float T = 0.f;
    #pragma unroll 8
    for (int rb = 0; rb < NRB; rb++) T += g_colpart[rb][b][k];
    if (mode == 0) {
        float gn = 0.5f * (g_pot[1][i] - logf(T));
        g_pot[1][i] = gn;
        g_wg[i] = bm[i] * __expf(gn);
    } else {
        g_c[1][i] = -bm[i] * logf(T);
    }
}

// ---------------- symmetric iteration: one row per block ----------------
__device__ __forceinline__ float block_row_sum(const __half* __restrict__ mrow,
                                               const float* __restrict__ wv)
{
    const int tid = threadIdx.x;
    const uint4*  M = (const uint4*)mrow;
    const float4* W = (const float4*)wv;
    float s = 0.f;
    #pragma unroll
    for (int rep = 0; rep < 2; rep++) {
        const int j = tid + rep * 128;
        uint4 m = M[j];
        float4 w0 = W[2 * j], w1 = W[2 * j + 1];
        float2 e0 = __half22float2(*reinterpret_cast<__half2*>(&m.x));
        float2 e1 = __half22float2(*reinterpret_cast<__half2*>(&m.y));
        float2 e2 = __half22float2(*reinterpret_cast<__half2*>(&m.z));
        float2 e3 = __half22float2(*reinterpret_cast<__half2*>(&m.w));
        s += e0.x * w0.x + e0.y * w0.y + e1.x * w0.z + e1.y * w0.w;
        s += e2.x * w1.x + e2.y * w1.y + e3.x * w1.z + e3.y * w1.w;
    }
    #pragma unroll
    for (int o = 16; o; o >>= 1) s += __shfl_xor_sync(0xffffffffu, s, o);
    __shared__ float red[4];
    if ((tid & 31) == 0) red[tid >> 5] = s;
    __syncthreads();
    return (red[0] + red[1]) + (red[2] + red[3]);
}

// slot 0: fx on Exx, slot 1: fy on Eyy (matrix selected IN-KERNEL)
__global__ void lse_sym(const float* __restrict__ meas, int slot, int par)
{
    const int b = blockIdx.y, row = blockIdx.x;
    const __half* mat = slot ? g_Eyy : g_Exx;
    const float* wi = g_wsym[par][slot] + b * NN;
    float tot = block_row_sum(mat + ((size_t)b * NN + row) * NN, wi);
    if (threadIdx.x == 0) {
        const int idx = b * NN + row;
        float pn = 0.5f * (g_pot[2 + slot][idx] - logf(tot));
        g_pot[2 + slot][idx] = pn;
        g_wsym[par ^ 1][slot][idx] = meas[idx] * __expf(pn);
    }
}

__global__ void eval_sym(const float* __restrict__ meas, int slot)
{
    const int b = blockIdx.y, row = blockIdx.x;
    const __half* mat = slot ? g_Eyy : g_Exx;
    const float* wi = g_wsym[0][slot] + b * NN;   // 10 iters -> final parity 0
    float tot = block_row_sum(mat + ((size_t)b * NN + row) * NN, wi);
    if (threadIdx.x == 0) {
        const int idx = b * NN + row;
        g_c[2 + slot][idx] = -meas[idx] * logf(tot);
    }
}

// ---------------- final scalar ----------------
__global__ void final_reduce(float* __restrict__ out)
{
    const int tid = threadIdx.x;
    float s = 0.f;
    for (int i = tid; i < BB * NN; i += 1024)
        s += (g_c[0][i] + g_c[1][i]) - (g_c[2][i] + g_c[3][i]);
    #pragma unroll
    for (int o = 16; o; o >>= 1) s += __shfl_xor_sync(0xffffffffu, s, o);
    __shared__ float sm[32];
    if ((tid & 31) == 0) sm[tid >> 5] = s;
    __syncthreads();
    if (tid < 32) {
        float v = sm[tid];
        #pragma unroll
        for (int o = 16; o; o >>= 1) v += __shfl_xor_sync(0xffffffffu, v, o);
        if (tid == 0) out[0] = v / (float)BB;
    }
}

// ---------------- launcher: phase-interleaved for L2 residency ----------------
extern "C" void kernel_launch(void* const* d_in, const int* in_sizes, int n_in,
                              void* d_out, int out_size)
{
    const float* x  = (const float*)d_in[0];
    const float* a  = (const float*)d_in[1];
    const float* y  = (const float*)d_in[2];
    const float* bm = (const float*)d_in[3];
    float* out = (float*)d_out;

    shift_kernel<<<dim3(16, BB), 128>>>(x, y);
    init_kernel<<<(BB * NN + 255) / 256, 256>>>(a, bm);

    dim3 bg(16, 16, BB);
    dim3 xg(NRB, BB);
    dim3 sg(NN, BB);

    // ---- xy phase (Exy resident in L2 throughout) ----
    build_xy<<<bg, 256>>>(x, y);
    for (int it = 0; it < 10; it++) {
        xy_main<<<xg, 256>>>(a, it & 1, 0);
        xy_fin<<<BB * NN / 256, 256>>>(bm, 0);
    }
    xy_main<<<xg, 256>>>(a, 0, 1);           // c0 + final colparts (wap parity 0)
    xy_fin<<<BB * NN / 256, 256>>>(bm, 1);   // c1

    // ---- xx phase ----
    build_sym<<<bg, 256>>>(x, 0);
    for (int it = 0; it < 10; it++)
        lse_sym<<<sg, 128>>>(a, 0, it & 1);
    eval_sym<<<sg, 128>>>(a, 0);             // c2

    // ---- yy phase ----
    build_sym<<<bg, 256>>>(y, 1);
    for (int it = 0; it < 10; it++)
        lse_sym<<<sg, 128>>>(bm, 1, it & 1);
    eval_sym<<<sg, 128>>>(bm, 1);            // c3

    final_reduce<<<1, 1024>>>(out);
}

// round 7
// speedup vs baseline: 1.8993x; 1.0835x over previous
#include <cuda_runtime.h>
#include <cuda_fp16.h>
#include <cuda_bf16.h>
#include <math.h>
#include <stdint.h>

#define BB 8
#define NN 2048
#define DD 32
#define RBS 16                      // rows per xy_main block
#define NRB (NN / RBS)              // 128 row-blocks

// ---------------- scratch (device globals; no allocations) ----------------
// NOTE: device symbols are ONLY dereferenced inside kernels (never passed from host).
__device__ __nv_bfloat16 g_Exy[(size_t)BB * NN * NN]; // exp((sh_l - dist(x_l,y_k))/2), bf16
__device__ __half g_Exx[(size_t)BB * NN * NN];        // exp(-dist/2), fp16
__device__ __half g_Eyy[(size_t)BB * NN * NN];
__device__ float g_shift[BB * NN];               // xy row shifts (x side)
__device__ float g_pot[4][BB * NN];              // 0:f 1:g 2:fx 3:fy
__device__ float g_wg[BB * NN];                  // b * exp(g)
__device__ float g_wap[2][BB * NN];              // a * exp(f - sh/2), parity buffered
__device__ float g_wsym[2][2][BB * NN];          // [parity][0:xx,1:yy]
__device__ float g_colpart[NRB][BB][NN];         // column partial sums
__device__ float g_c[4][BB * NN];                // eval contributions

// ---------------- small helpers ----------------
__device__ __forceinline__ uint32_t f2tf32(float f) {
    uint32_t r;
    asm("cvt.rna.tf32.f32 %0, %1;" : "=r"(r) : "f"(f));
    return r;
}
__device__ __forceinline__ void mma_tf32(float d[4],
    uint32_t a0, uint32_t a1, uint32_t a2, uint32_t a3, uint32_t b0, uint32_t b1)
{
    asm("mma.sync.aligned.m16n8k8.row.col.f32.tf32.tf32.f32 "
        "{%0,%1,%2,%3}, {%4,%5,%6,%7}, {%8,%9}, {%0,%1,%2,%3};"
        : "+f"(d[0]), "+f"(d[1]), "+f"(d[2]), "+f"(d[3])
        : "r"(a0), "r"(a1), "r"(a2), "r"(a3), "r"(b0), "r"(b1));
}

// ---------------- row shifts: sampled min dist over first 128 y's ----------------
__global__ void shift_kernel(const float* __restrict__ x, const float* __restrict__ y)
{
    const int b = blockIdx.y;
    const int l = blockIdx.x * 128 + threadIdx.x;
    const float* Pb = x + (size_t)b * NN * DD;
    const float* Qb = y + (size_t)b * NN * DD;

    __shared__ float sq[128][DD + 1];
    for (int i = threadIdx.x; i < 128 * DD; i += 128)
        sq[i >> 5][i & 31] = Qb[i];
    __syncthreads();

    float p[DD];
    #pragma unroll
    for (int d = 0; d < DD; d++) p[d] = Pb[(size_t)l * DD + d];

    float mn = 3.4e38f;
    for (int k = 0; k < 128; k++) {
        float acc = 0.f;
        #pragma unroll
        for (int d = 0; d < DD; d++) {
            float df = p[d] - sq[k][d];
            acc = fmaf(df, df, acc);
        }
        mn = fminf(mn, acc);
    }
    g_shift[b * NN + l] = mn;
}

// ---------------- init ----------------
__global__ void init_kernel(const float* __restrict__ a, const float* __restrict__ bm)
{
    int i = blockIdx.x * 256 + threadIdx.x;
    if (i < BB * NN) {
        g_pot[0][i] = 0.f; g_pot[1][i] = 0.f;
        g_pot[2][i] = 0.f; g_pot[3][i] = 0.f;
        g_wg[i] = bm[i];
        g_wap[0][i] = a[i] * __expf(-0.5f * g_shift[i]);
        g_wsym[0][0][i] = a[i];
        g_wsym[0][1][i] = bm[i];
    }
}

// ---------------- tensor-core build core ----------------
// block 256 (8 warps), tile 128x128 per batch. Warp w owns 16 cols.
// tf32 split: dot = hi*hi + hi*lo + lo*hi  (error ~1e-5 absolute, fp32-like)
// OUT: 0 -> g_Exy (bf16, row-shifted); 1 -> g_Exx (fp16); 2 -> g_Eyy (fp16)
template <int USE_SHIFT, int OUT>
__device__ __forceinline__ void build_core(const float* __restrict__ P,
                                           const float* __restrict__ Q)
{
    __shared__ float sp[128][DD + 4];   // pad 36: conflict-free frag loads
    __shared__ float sq[128][DD + 4];
    __shared__ float snp[128], snq[128];

    const int b  = blockIdx.z;
    const int l0 = blockIdx.y * 128;
    const int k0 = blockIdx.x * 128;
    const int tid = threadIdx.x;
    const float* Pb = P + (size_t)b * NN * DD;
    const float* Qb = Q + (size_t)b * NN * DD;

    for (int i = tid; i < 128 * DD; i += 256) {
        int r = i >> 5, d = i & 31;
        sp[r][d] = Pb[(size_t)(l0 + r) * DD + d];
        sq[r][d] = Qb[(size_t)(k0 + r) * DD + d];
    }
    __syncthreads();

    if (tid < 128) {
        float s = 0.f;
        #pragma unroll
        for (int d = 0; d < DD; d++) s = fmaf(sp[tid][d], sp[tid][d], s);
        snp[tid] = s;
    } else {
        int r = tid - 128;
        float s = 0.f;
        #pragma unroll
        for (int d = 0; d < DD; d++) s = fmaf(sq[r][d], sq[r][d], s);
        snq[r] = s;
    }
    __syncthreads();

    const int warp = tid >> 5, lane = tid & 31;
    const int g = lane >> 2, tg = lane & 3;     // groupID, threadInGroup
    const int nb = warp * 16;                    // warp's col base within tile

    float acc[8][2][4];
    #pragma unroll
    for (int r = 0; r < 8; r++)
        #pragma unroll
        for (int c = 0; c < 2; c++)
            #pragma unroll
            for (int q = 0; q < 4; q++) acc[r][c][q] = 0.f;

    #pragma unroll
    for (int kt = 0; kt < 4; kt++) {
        const int kc = kt * 8;
        // B frags (y as k x n col-major: B[d][n] = sq[n][d])
        uint32_t bh[2][2], bl[2][2];
        #pragma unroll
        for (int c = 0; c < 2; c++) {
            float f0 = sq[nb + c * 8 + g][kc + tg];
            float f1 = sq[nb + c * 8 + g][kc + tg + 4];
            bh[c][0] = f2tf32(f0); bl[c][0] = f2tf32(f0 - __uint_as_float(bh[c][0]));
            bh[c][1] = f2tf32(f1); bl[c][1] = f2tf32(f1 - __uint_as_float(bh[c][1]));
        }
        #pragma unroll
        for (int r = 0; r < 8; r++) {
            float a00 = sp[r * 16 + g][kc + tg];        // a0: (row g,   col tg)
            float a10 = sp[r * 16 + g + 8][kc + tg];    // a1: (row g+8, col tg)
            float a01 = sp[r * 16 + g][kc + tg + 4];    // a2: (row g,   col tg+4)
            float a11 = sp[r * 16 + g + 8][kc + tg + 4];// a3: (row g+8, col tg+4)
            uint32_t h0 = f2tf32(a00), h1 = f2tf32(a10), h2 = f2tf32(a01), h3 = f2tf32(a11);
            uint32_t l0r = f2tf32(a00 - __uint_as_float(h0));
            uint32_t l1r = f2tf32(a10 - __uint_as_float(h1));
            uint32_t l2r = f2tf32(a01 - __uint_as_float(h2));
            uint32_t l3r = f2tf32(a11 - __uint_as_float(h3));
            #pragma unroll
            for (int c = 0; c < 2; c++) {
                mma_tf32(acc[r][c], h0, h1, h2, h3, bh[c][0], bh[c][1]);    // hi*hi
                mma_tf32(acc[r][c], h0, h1, h2, h3, bl[c][0], bl[c][1]);    // hi*lo
                mma_tf32(acc[r][c], l0r, l1r, l2r, l3r, bh[c][0], bh[c][1]);// lo*hi
            }
        }
    }

    // epilogue: dist -> exp -> packed store
    const size_t base = (size_t)b * NN * NN;
    #pragma unroll
    for (int r = 0; r < 8; r++) {
        const int row0 = l0 + r * 16 + g;
        const int row1 = row0 + 8;
        const float nx0 = snp[r * 16 + g], nx1 = snp[r * 16 + g + 8];
        const float sh0 = USE_SHIFT ? g_shift[b * NN + row0] : 0.f;
        const float sh1 = USE_SHIFT ? g_shift[b * NN + row1] : 0.f;
        #pragma unroll
        for (int c = 0; c < 2; c++) {
            const int col = k0 + nb + c * 8 + tg * 2;
            const float ny0 = snq[nb + c * 8 + tg * 2];
            const float ny1 = snq[nb + c * 8 + tg * 2 + 1];
            float e00 = __expf(0.5f * (sh0 - fmaxf(nx0 + ny0 - 2.f * acc[r][c][0], 0.f)));
            float e01 = __expf(0.5f * (sh0 - fmaxf(nx0 + ny1 - 2.f * acc[r][c][1], 0.f)));
            float e10 = __expf(0.5f * (sh1 - fmaxf(nx1 + ny0 - 2.f * acc[r][c][2], 0.f)));
            float e11 = __expf(0.5f * (sh1 - fmaxf(nx1 + ny1 - 2.f * acc[r][c][3], 0.f)));
            if (OUT == 0) {
                *(__nv_bfloat162*)&g_Exy[base + (size_t)row0 * NN + col] =
                    __floats2bfloat162_rn(e00, e01);
                *(__nv_bfloat162*)&g_Exy[base + (size_t)row1 * NN + col] =
                    __floats2bfloat162_rn(e10, e11);
            } else {
                __half* M = (OUT == 1) ? g_Exx : g_Eyy;
                *(__half2*)&M[base + (size_t)row0 * NN + col] = __floats2half2_rn(e00, e01);
                *(__half2*)&M[base + (size_t)row1 * NN + col] = __floats2half2_rn(e10, e11);
            }
        }
    }
}

__global__ void __launch_bounds__(256) build_xy(const float* __restrict__ x,
                                                const float* __restrict__ y)
{ build_core<1, 0>(x, y); }
__global__ void __launch_bounds__(256) build_xx(const float* __restrict__ x)
{ build_core<0, 1>(x, x); }
__global__ void __launch_bounds__(256) build_yy(const float* __restrict__ y)
{ build_core<0, 2>(y, y); }

// ---------------- xy main pass: row sums (f side) + column partials (g side) ----------------
// grid (NRB, BB), block 256 = 8 warps; warp w covers cols [w*256, w*256+256)
// mode 0: Sinkhorn iter; mode 1: eval (c0 + final colparts)
__global__ void xy_main(const float* __restrict__ a, int par, int mode)
{
    const int b = blockIdx.y, rb = blockIdx.x;
    const int tid = threadIdx.x, warp = tid >> 5, lane = tid & 31;
    const int c0 = warp * 256 + lane * 8;

    __shared__ float swap_s[RBS];
    __shared__ float rowpart[RBS][9];

    if (tid < RBS) swap_s[tid] = g_wap[par][b * NN + rb * RBS + tid];

    float4 wg0 = *(const float4*)&g_wg[b * NN + c0];
    float4 wg1 = *(const float4*)&g_wg[b * NN + c0 + 4];
    __syncthreads();

    const __nv_bfloat16* Srow = g_Exy + ((size_t)b * NN + rb * RBS) * NN + c0;

    float colacc[8];
    #pragma unroll
    for (int j = 0; j < 8; j++) colacc[j] = 0.f;

    #pragma unroll 2
    for (int g4 = 0; g4 < RBS / 4; g4++) {
        float rd[4];
        #pragma unroll
        for (int rr = 0; rr < 4; rr++) {
            const int r = g4 * 4 + rr;
            uint4 m = __ldg((const uint4*)(Srow + (size_t)r * NN));
            float2 e0 = __bfloat1622float2(*reinterpret_cast<__nv_bfloat162*>(&m.x));
            float2 e1 = __bfloat1622float2(*reinterpret_cast<__nv_bfloat162*>(&m.y));
            float2 e2 = __bfloat1622float2(*reinterpret_cast<__nv_bfloat162*>(&m.z));
            float2 e3 = __bfloat1622float2(*reinterpret_cast<__nv_bfloat162*>(&m.w));
            float wr = swap_s[r];
            float s = 0.f;
            s = fmaf(e0.x, wg0.x, s); s = fmaf(e0.y, wg0.y, s);
            s = fmaf(e1.x, wg0.z, s); s = fmaf(e1.y, wg0.w, s);
            s = fmaf(e2.x, wg1.x, s); s = fmaf(e2.y, wg1.y, s);
            s = fmaf(e3.x, wg1.z, s); s = fmaf(e3.y, wg1.w, s);
            rd[rr] = s;
            colacc[0] = fmaf(e0.x, wr, colacc[0]); colacc[1] = fmaf(e0.y, wr, colacc[1]);
            colacc[2] = fmaf(e1.x, wr, colacc[2]); colacc[3] = fmaf(e1.y, wr, colacc[3]);
            colacc[4] = fmaf(e2.x, wr, colacc[4]); colacc[5] = fmaf(e2.y, wr, colacc[5]);
            colacc[6] = fmaf(e3.x, wr, colacc[6]); colacc[7] = fmaf(e3.y, wr, colacc[7]);
        }
        #pragma unroll
        for (int o = 16; o; o >>= 1) {
            #pragma unroll
            for (int rr = 0; rr < 4; rr++)
                rd[rr] += __shfl_xor_sync(0xffffffffu, rd[rr], o);
        }
        if (lane == 0) {
            #pragma unroll
            for (int rr = 0; rr < 4; rr++) rowpart[g4 * 4 + rr][warp] = rd[rr];
        }
    }

    float* cp = &g_colpart[rb][b][c0];
    *(float4*)cp       = make_float4(colacc[0], colacc[1], colacc[2], colacc[3]);
    *(float4*)(cp + 4) = make_float4(colacc[4], colacc[5], colacc[6], colacc[7]);

    __syncthreads();

    if (tid < RBS) {
        const int row = rb * RBS + tid;
        const int idx = b * NN + row;
        float tot = 0.f;
        #pragma unroll
        for (int w = 0; w < 8; w++) tot += rowpart[tid][w];
        const float sh = g_shift[idx];
        if (mode == 0) {
            float fn = 0.5f * (g_pot[0][idx] - logf(tot) + 0.5f * sh);
            g_pot[0][idx] = fn;
            g_wap[par ^ 1][idx] = a[idx] * __expf(fn - 0.5f * sh);
        } else {
            g_c[0][idx] = a[idx] * (0.5f * sh - logf(tot));
        }
    }
}

// ---------------- xy finalize: reduce column partials, update g / emit c1 ----------------
__global__ void xy_fin(const float* __restrict__ bm, int mode)
{
    const int i = blockIdx.x * 256 + threadIdx.x;       // i = b*NN + k
    const int b = i >> 11, k = i & (NN - 1);
    float T = 0.f;
    #pragma unroll 8
    for (int rb = 0; rb < NRB; rb++) T += g_colpart[rb][b][k];
    if (mode == 0) {
        float gn = 0.5f * (g_pot[1][i] - logf(T));
        g_pot[1][i] = gn;
        g_wg[i] = bm[i] * __expf(gn);
    } else {
        g_c[1][i] = -bm[i] * logf(T);
    }
}

// ---------------- symmetric iteration: one row per block ----------------
__device__ __forceinline__ float block_row_sum(const __half* __restrict__ mrow,
                                               const float* __restrict__ wv)
{
    const int tid = threadIdx.x;
    const float4* W = (const float4*)wv;
    float s = 0.f;
    #pragma unroll
    for (int rep = 0; rep < 2; rep++) {
        const int j = tid + rep * 128;
        uint4 m = __ldg((const uint4*)mrow + j);
        float4 w0 = W[2 * j], w1 = W[2 * j + 1];
        float2 e0 = __half22float2(*reinterpret_cast<__half2*>(&m.x));
        float2 e1 = __half22float2(*reinterpret_cast<__half2*>(&m.y));
        float2 e2 = __half22float2(*reinterpret_cast<__half2*>(&m.z));
        float2 e3 = __half22float2(*reinterpret_cast<__half2*>(&m.w));
        s += e0.x * w0.x + e0.y * w0.y + e1.x * w0.z + e1.y * w0.w;
        s += e2.x * w1.x + e2.y * w1.y + e3.x * w1.z + e3.y * w1.w;
    }
    #pragma unroll
    for (int o = 16; o; o >>= 1) s += __shfl_xor_sync(0xffffffffu, s, o);
    __shared__ float red[4];
    if ((tid & 31) == 0) red[tid >> 5] = s;
    __syncthreads();
    return (red[0] + red[1]) + (red[2] + red[3]);
}

// slot 0: fx on Exx, slot 1: fy on Eyy (matrix selected IN-KERNEL)
__global__ void lse_sym(const float* __restrict__ meas, int slot, int par)
{
    const int b = blockIdx.y, row = blockIdx.x;
    const __half* mat = slot ? g_Eyy : g_Exx;
    const float* wi = g_wsym[par][slot] + b * NN;
    float tot = block_row_sum(mat + ((size_t)b * NN + row) * NN, wi);
    if (threadIdx.x == 0) {
        const int idx = b * NN + row;
        float pn = 0.5f * (g_pot[2 + slot][idx] - logf(tot));
        g_pot[2 + slot][idx] = pn;
        g_wsym[par ^ 1][slot][idx] = meas[idx] * __expf(pn);
    }
}

__global__ void eval_sym(const float* __restrict__ meas, int slot)
{
    const int b = blockIdx.y, row = blockIdx.x;
    const __half* mat = slot ? g_Eyy : g_Exx;
    const float* wi = g_wsym[0][slot] + b * NN;   // 10 iters -> final parity 0
    float tot = block_row_sum(mat + ((size_t)b * NN + row) * NN, wi);
    if (threadIdx.x == 0) {
        const int idx = b * NN + row;
        g_c[2 + slot][idx] = -meas[idx] * logf(tot);
    }
}

// ---------------- final scalar ----------------
__global__ void final_reduce(float* __restrict__ out)
{
    const int tid = threadIdx.x;
    float s = 0.f;
    for (int i = tid; i < BB * NN; i += 1024)
        s += (g_c[0][i] + g_c[1][i]) - (g_c[2][i] + g_c[3][i]);
    #pragma unroll
    for (int o = 16; o; o >>= 1) s += __shfl_xor_sync(0xffffffffu, s, o);
    __shared__ float sm[32];
    if ((tid & 31) == 0) sm[tid >> 5] = s;
    __syncthreads();
    if (tid < 32) {
        float v = sm[tid];
        #pragma unroll
        for (int o = 16; o; o >>= 1) v += __shfl_xor_sync(0xffffffffu, v, o);
        if (tid == 0) out[0] = v / (float)BB;
    }
}

// ---------------- launcher: phase-interleaved for L2 residency ----------------
extern "C" void kernel_launch(void* const* d_in, const int* in_sizes, int n_in,
                              void* d_out, int out_size)
{
    const float* x  = (const float*)d_in[0];
    const float* a  = (const float*)d_in[1];
    const float* y  = (const float*)d_in[2];
    const float* bm = (const float*)d_in[3];
    float* out = (float*)d_out;

    shift_kernel<<<dim3(16, BB), 128>>>(x, y);
    init_kernel<<<(BB * NN + 255) / 256, 256>>>(a, bm);

    dim3 bg(16, 16, BB);
    dim3 xg(NRB, BB);
    dim3 sg(NN, BB);

    // ---- xy phase (Exy resident in L2 throughout) ----
    build_xy<<<bg, 256>>>(x, y);
    for (int it = 0; it < 10; it++) {
        xy_main<<<xg, 256>>>(a, it & 1, 0);
        xy_fin<<<BB * NN / 256, 256>>>(bm, 0);
    }
    xy_main<<<xg, 256>>>(a, 0, 1);           // c0 + final colparts (wap parity 0)
    xy_fin<<<BB * NN / 256, 256>>>(bm, 1);   // c1

    // ---- xx phase ----
    build_xx<<<bg, 256>>>(x);
    for (int it = 0; it < 10; it++)
        lse_sym<<<sg, 128>>>(a, 0, it & 1);
    eval_sym<<<sg, 128>>>(a, 0);             // c2

    // ---- yy phase ----
    build_yy<<<bg, 256>>>(y);
    for (int it = 0; it < 10; it++)
        lse_sym<<<sg, 128>>>(bm, 1, it & 1);
    eval_sym<<<sg, 128>>>(bm, 1);            // c3

    final_reduce<<<1, 1024>>>(out);
}

// round 8
// speedup vs baseline: 1.9870x; 1.0462x over previous
#include <cuda_runtime.h>
#include <cuda_fp16.h>
#include <cuda_bf16.h>
#include <math.h>
#include <stdint.h>

#define BB 8
#define NN 2048
#define DD 32
#define RBS 16                      // rows per row-block
#define NRB (NN / RBS)              // 128 row-blocks

// ---------------- scratch (device globals; no allocations) ----------------
// NOTE: device symbols are ONLY dereferenced inside kernels (never passed from host).
__device__ __nv_bfloat16 g_Exy[(size_t)BB * NN * NN]; // exp((sh_l - dist(x_l,y_k))/2), bf16
__device__ __half g_Exx[(size_t)BB * NN * NN];        // exp(-dist/2), fp16 (upper tiles valid)
__device__ __half g_Eyy[(size_t)BB * NN * NN];
__device__ float g_shift[BB * NN];               // xy row shifts (x side)
__device__ float g_pot[4][BB * NN];              // 0:f 1:g 2:fx 3:fy
__device__ float g_wg[BB * NN];                  // b * exp(g)
__device__ float g_wap[2][BB * NN];              // a * exp(f - sh/2), parity buffered
__device__ float g_wsym[2][2][BB * NN];          // [parity][0:xx,1:yy]
__device__ float g_colpart[NRB][BB][NN];         // xy column partial sums
__device__ float g_colpartS[2][NRB][BB][NN];     // sym column partials per slot
__device__ float g_symrow[2][BB * NN];           // sym row sums (cols >= start part)
__device__ float g_c[4][BB * NN];                // eval contributions

// ---------------- small helpers ----------------
__device__ __forceinline__ uint32_t f2tf32(float f) {
    uint32_t r;
    asm("cvt.rna.tf32.f32 %0, %1;" : "=r"(r) : "f"(f));
    return r;
}
__device__ __forceinline__ void mma_tf32(float d[4],
    uint32_t a0, uint32_t a1, uint32_t a2, uint32_t a3, uint32_t b0, uint32_t b1)
{
    asm("mma.sync.aligned.m16n8k8.row.col.f32.tf32.tf32.f32 "
        "{%0,%1,%2,%3}, {%4,%5,%6,%7}, {%8,%9}, {%0,%1,%2,%3};"
        : "+f"(d[0]), "+f"(d[1]), "+f"(d[2]), "+f"(d[3])
        : "r"(a0), "r"(a1), "r"(a2), "r"(a3), "r"(b0), "r"(b1));
}

// ---------------- row shifts: sampled min dist over first 128 y's ----------------
__global__ void shift_kernel(const float* __restrict__ x, const float* __restrict__ y)
{
    const int b = blockIdx.y;
    const int l = blockIdx.x * 128 + threadIdx.x;
    const float* Pb = x + (size_t)b * NN * DD;
    const float* Qb = y + (size_t)b * NN * DD;

    __shared__ float sq[128][DD + 1];
    for (int i = threadIdx.x; i < 128 * DD; i += 128)
        sq[i >> 5][i & 31] = Qb[i];
    __syncthreads();

    float p[DD];
    #pragma unroll
    for (int d = 0; d < DD; d++) p[d] = Pb[(size_t)l * DD + d];

    float mn = 3.4e38f;
    for (int k = 0; k < 128; k++) {
        float acc = 0.f;
        #pragma unroll
        for (int d = 0; d < DD; d++) {
            float df = p[d] - sq[k][d];
            acc = fmaf(df, df, acc);
        }
        mn = fminf(mn, acc);
    }
    g_shift[b * NN + l] = mn;
}

// ---------------- init ----------------
__global__ void init_kernel(const float* __restrict__ a, const float* __restrict__ bm)
{
    int i = blockIdx.x * 256 + threadIdx.x;
    if (i < BB * NN) {
        g_pot[0][i] = 0.f; g_pot[1][i] = 0.f;
        g_pot[2][i] = 0.f; g_pot[3][i] = 0.f;
        g_wg[i] = bm[i];
        g_wap[0][i] = a[i] * __expf(-0.5f * g_shift[i]);
        g_wsym[0][0][i] = a[i];
        g_wsym[0][1][i] = bm[i];
    }
}

// ---------------- tensor-core build core ----------------
// block 256 (8 warps), tile 128x128 per batch. tf32 3-product split (fp32-like).
// OUT: 0 -> g_Exy (bf16, row-shifted); 1 -> g_Exx (fp16); 2 -> g_Eyy (fp16)
template <int USE_SHIFT, int OUT>
__device__ __forceinline__ void build_core(const float* __restrict__ P,
                                           const float* __restrict__ Q)
{
    __shared__ float sp[128][DD + 4];
    __shared__ float sq[128][DD + 4];
    __shared__ float snp[128], snq[128];

    const int b  = blockIdx.z;
    const int l0 = blockIdx.y * 128;
    const int k0 = blockIdx.x * 128;
    const int tid = threadIdx.x;
    const float* Pb = P + (size_t)b * NN * DD;
    const float* Qb = Q + (size_t)b * NN * DD;

    for (int i = tid; i < 128 * DD; i += 256) {
        int r = i >> 5, d = i & 31;
        sp[r][d] = Pb[(size_t)(l0 + r) * DD + d];
        sq[r][d] = Qb[(size_t)(k0 + r) * DD + d];
    }
    __syncthreads();

    if (tid < 128) {
        float s = 0.f;
        #pragma unroll
        for (int d = 0; d < DD; d++) s = fmaf(sp[tid][d], sp[tid][d], s);
        snp[tid] = s;
    } else {
        int r = tid - 128;
        float s = 0.f;
        #pragma unroll
        for (int d = 0; d < DD; d++) s = fmaf(sq[r][d], sq[r][d], s);
        snq[r] = s;
    }
    __syncthreads();

    const int warp = tid >> 5, lane = tid & 31;
    const int g = lane >> 2, tg = lane & 3;
    const int nb = warp * 16;

    float acc[8][2][4];
    #pragma unroll
    for (int r = 0; r < 8; r++)
        #pragma unroll
        for (int c = 0; c < 2; c++)
            #pragma unroll
            for (int q = 0; q < 4; q++) acc[r][c][q] = 0.f;

    #pragma unroll
    for (int kt = 0; kt < 4; kt++) {
        const int kc = kt * 8;
        uint32_t bh[2][2], bl[2][2];
        #pragma unroll
        for (int c = 0; c < 2; c++) {
            float f0 = sq[nb + c * 8 + g][kc + tg];
            float f1 = sq[nb + c * 8 + g][kc + tg + 4];
            bh[c][0] = f2tf32(f0); bl[c][0] = f2tf32(f0 - __uint_as_float(bh[c][0]));
            bh[c][1] = f2tf32(f1); bl[c][1] = f2tf32(f1 - __uint_as_float(bh[c][1]));
        }
        #pragma unroll
        for (int r = 0; r < 8; r++) {
            float a00 = sp[r * 16 + g][kc + tg];
            float a10 = sp[r * 16 + g + 8][kc + tg];
            float a01 = sp[r * 16 + g][kc + tg + 4];
            float a11 = sp[r * 16 + g + 8][kc + tg + 4];
            uint32_t h0 = f2tf32(a00), h1 = f2tf32(a10), h2 = f2tf32(a01), h3 = f2tf32(a11);
            uint32_t l0r = f2tf32(a00 - __uint_as_float(h0));
            uint32_t l1r = f2tf32(a10 - __uint_as_float(h1));
            uint32_t l2r = f2tf32(a01 - __uint_as_float(h2));
            uint32_t l3r = f2tf32(a11 - __uint_as_float(h3));
            #pragma unroll
            for (int c = 0; c < 2; c++) {
                mma_tf32(acc[r][c], h0, h1, h2, h3, bh[c][0], bh[c][1]);
                mma_tf32(acc[r][c], h0, h1, h2, h3, bl[c][0], bl[c][1]);
                mma_tf32(acc[r][c], l0r, l1r, l2r, l3r, bh[c][0], bh[c][1]);
            }
        }
    }

    const size_t base = (size_t)b * NN * NN;
    #pragma unroll
    for (int r = 0; r < 8; r++) {
        const int row0 = l0 + r * 16 + g;
        const int row1 = row0 + 8;
        const float nx0 = snp[r * 16 + g], nx1 = snp[r * 16 + g + 8];
        const float sh0 = USE_SHIFT ? g_shift[b * NN + row0] : 0.f;
        const float sh1 = USE_SHIFT ? g_shift[b * NN + row1] : 0.f;
        #pragma unroll
        for (int c = 0; c < 2; c++) {
            const int col = k0 + nb + c * 8 + tg * 2;
            const float ny0 = snq[nb + c * 8 + tg * 2];
            const float ny1 = snq[nb + c * 8 + tg * 2 + 1];
            float e00 = __expf(0.5f * (sh0 - fmaxf(nx0 + ny0 - 2.f * acc[r][c][0], 0.f)));
            float e01 = __expf(0.5f * (sh0 - fmaxf(nx0 + ny1 - 2.f * acc[r][c][1], 0.f)));
            float e10 = __expf(0.5f * (sh1 - fmaxf(nx1 + ny0 - 2.f * acc[r][c][2], 0.f)));
            float e11 = __expf(0.5f * (sh1 - fmaxf(nx1 + ny1 - 2.f * acc[r][c][3], 0.f)));
            if (OUT == 0) {
                *(__nv_bfloat162*)&g_Exy[base + (size_t)row0 * NN + col] =
                    __floats2bfloat162_rn(e00, e01);
                *(__nv_bfloat162*)&g_Exy[base + (size_t)row1 * NN + col] =
                    __floats2bfloat162_rn(e10, e11);
            } else {
                __half* M = (OUT == 1) ? g_Exx : g_Eyy;
                *(__half2*)&M[base + (size_t)row0 * NN + col] = __floats2half2_rn(e00, e01);
                *(__half2*)&M[base + (size_t)row1 * NN + col] = __floats2half2_rn(e10, e11);
            }
        }
    }
}

__global__ void __launch_bounds__(256) build_xy(const float* __restrict__ x,
                                                const float* __restrict__ y)
{ build_core<1, 0>(x, y); }
// Sym builds: only upper-staircase 128-tiles needed (cols >= row-block start)
__global__ void __launch_bounds__(256) build_xx(const float* __restrict__ x)
{ if (blockIdx.x < blockIdx.y) return; build_core<0, 1>(x, x); }
__global__ void __launch_bounds__(256) build_yy(const float* __restrict__ y)
{ if (blockIdx.x < blockIdx.y) return; build_core<0, 2>(y, y); }

// ---------------- xy main pass: row sums (f side) + column partials (g side) ----------------
__global__ void xy_main(const float* __restrict__ a, int par, int mode)
{
    const int b = blockIdx.y, rb = blockIdx.x;
    const int tid = threadIdx.x, warp = tid >> 5, lane = tid & 31;
    const int c0 = warp * 256 + lane * 8;

    __shared__ float swap_s[RBS];
    __shared__ float rowpart[RBS][9];

    if (tid < RBS) swap_s[tid] = g_wap[par][b * NN + rb * RBS + tid];

    float4 wg0 = *(const float4*)&g_wg[b * NN + c0];
    float4 wg1 = *(const float4*)&g_wg[b * NN + c0 + 4];
    __syncthreads();

    const __nv_bfloat16* Srow = g_Exy + ((size_t)b * NN + rb * RBS) * NN + c0;

    float colacc[8];
    #pragma unroll
    for (int j = 0; j < 8; j++) colacc[j] = 0.f;

    #pragma unroll 2
    for (int g4 = 0; g4 < RBS / 4; g4++) {
        float rd[4];
        #pragma unroll
        for (int rr = 0; rr < 4; rr++) {
            const int r = g4 * 4 + rr;
            uint4 m = __ldg((const uint4*)(Srow + (size_t)r * NN));
            float2 e0 = __bfloat1622float2(*reinterpret_cast<__nv_bfloat162*>(&m.x));
            float2 e1 = __bfloat1622float2(*reinterpret_cast<__nv_bfloat162*>(&m.y));
            float2 e2 = __bfloat1622float2(*reinterpret_cast<__nv_bfloat162*>(&m.z));
            float2 e3 = __bfloat1622float2(*reinterpret_cast<__nv_bfloat162*>(&m.w));
            float wr = swap_s[r];
            float s = 0.f;
            s = fmaf(e0.x, wg0.x, s); s = fmaf(e0.y, wg0.y, s);
            s = fmaf(e1.x, wg0.z, s); s = fmaf(e1.y, wg0.w, s);
            s = fmaf(e2.x, wg1.x, s); s = fmaf(e2.y, wg1.y, s);
            s = fmaf(e3.x, wg1.z, s); s = fmaf(e3.y, wg1.w, s);
            rd[rr] = s;
            colacc[0] = fmaf(e0.x, wr, colacc[0]); colacc[1] = fmaf(e0.y, wr, colacc[1]);
            colacc[2] = fmaf(e1.x, wr, colacc[2]); colacc[3] = fmaf(e1.y, wr, colacc[3]);
            colacc[4] = fmaf(e2.x, wr, colacc[4]); colacc[5] = fmaf(e2.y, wr, colacc[5]);
            colacc[6] = fmaf(e3.x, wr, colacc[6]); colacc[7] = fmaf(e3.y, wr, colacc[7]);
        }
        #pragma unroll
        for (int o = 16; o; o >>= 1) {
            #pragma unroll
            for (int rr = 0; rr < 4; rr++)
                rd[rr] += __shfl_xor_sync(0xffffffffu, rd[rr], o);
        }
        if (lane == 0) {
            #pragma unroll
            for (int rr = 0; rr < 4; rr++) rowpart[g4 * 4 + rr][warp] = rd[rr];
        }
    }

    float* cp = &g_colpart[rb][b][c0];
    *(float4*)cp       = make_float4(colacc[0], colacc[1], colacc[2], colacc[3]);
    *(float4*)(cp + 4) = make_float4(colacc[4], colacc[5], colacc[6], colacc[7]);

    __syncthreads();

    if (tid < RBS) {
        const int row = rb * RBS + tid;
        const int idx = b * NN + row;
        float tot = 0.f;
        #pragma unroll
        for (int w = 0; w < 8; w++) tot += rowpart[tid][w];
        const float sh = g_shift[idx];
        if (mode == 0) {
            float fn = 0.5f * (g_pot[0][idx] - logf(tot) + 0.5f * sh);
            g_pot[0][idx] = fn;
            g_wap[par ^ 1][idx] = a[idx] * __expf(fn - 0.5f * sh);
        } else {
            g_c[0][idx] = a[idx] * (0.5f * sh - logf(tot));
        }
    }
}

// ---------------- xy finalize ----------------
__global__ void xy_fin(const float* __restrict__ bm, int mode)
{
    const int i = blockIdx.x * 256 + threadIdx.x;       // i = b*NN + k
    const int b = i >> 11, k = i & (NN - 1);
    float T = 0.f;
    #pragma unroll 8
    for (int rb = 0; rb < NRB; rb++) T += g_colpart[rb][b][k];
    if (mode == 0) {
        float gn = 0.5f * (g_pot[1][i] - logf(T));
        g_pot[1][i] = gn;
        g_wg[i] = bm[i] * __expf(gn);
    } else {
        g_c[1][i] = -bm[i] * logf(T);
    }
}

// ---------------- sym main pass (SYMV, upper triangle only) ----------------
// grid (NRB/2, BB, 2). Block bx handles row-blocks {bx, NRB-1-bx}, cols >= 16*i each.
// Row-sums (cols >= start) -> g_symrow; column partials -> g_colpartS[slot][i].
__global__ void sym_main(int par)
{
    const int slot = blockIdx.z, b = blockIdx.y, bx = blockIdx.x;
    const int tid = threadIdx.x, warp = tid >> 5, lane = tid & 31;
    const int c0 = warp * 256 + lane * 8;
    const __half* M = slot ? g_Eyy : g_Exx;
    const float* wv = g_wsym[par][slot] + b * NN;

    __shared__ float swap_s[RBS];
    __shared__ float rowpart[RBS][9];

    const float4 w0 = *(const float4*)&wv[c0];
    const float4 w1 = *(const float4*)&wv[c0 + 4];

    #pragma unroll
    for (int s = 0; s < 2; s++) {
        const int i = s ? (NRB - 1 - bx) : bx;
        const int start = i * RBS;
        const bool act = (c0 >= start);

        __syncthreads();
        if (tid < RBS) swap_s[tid] = wv[start + tid];
        __syncthreads();

        const __half* Srow = M + ((size_t)b * NN + start) * NN + c0;

        float colacc[8];
        #pragma unroll
        for (int j = 0; j < 8; j++) colacc[j] = 0.f;

        #pragma unroll 2
        for (int g4 = 0; g4 < RBS / 4; g4++) {
            float rd[4];
            #pragma unroll
            for (int rr = 0; rr < 4; rr++) {
                const int r = g4 * 4 + rr;
                uint4 m = act ? __ldg((const uint4*)(Srow + (size_t)r * NN))
                              : make_uint4(0u, 0u, 0u, 0u);
                float2 e0 = __half22float2(*reinterpret_cast<__half2*>(&m.x));
                float2 e1 = __half22float2(*reinterpret_cast<__half2*>(&m.y));
                float2 e2 = __half22float2(*reinterpret_cast<__half2*>(&m.z));
                float2 e3 = __half22float2(*reinterpret_cast<__half2*>(&m.w));
                float wr = swap_s[r];
                float sacc = 0.f;
                sacc = fmaf(e0.x, w0.x, sacc); sacc = fmaf(e0.y, w0.y, sacc);
                sacc = fmaf(e1.x, w0.z, sacc); sacc = fmaf(e1.y, w0.w, sacc);
                sacc = fmaf(e2.x, w1.x, sacc); sacc = fmaf(e2.y, w1.y, sacc);
                sacc = fmaf(e3.x, w1.z, sacc); sacc = fmaf(e3.y, w1.w, sacc);
                rd[rr] = sacc;
                colacc[0] = fmaf(e0.x, wr, colacc[0]); colacc[1] = fmaf(e0.y, wr, colacc[1]);
                colacc[2] = fmaf(e1.x, wr, colacc[2]); colacc[3] = fmaf(e1.y, wr, colacc[3]);
                colacc[4] = fmaf(e2.x, wr, colacc[4]); colacc[5] = fmaf(e2.y, wr, colacc[5]);
                colacc[6] = fmaf(e3.x, wr, colacc[6]); colacc[7] = fmaf(e3.y, wr, colacc[7]);
            }
            #pragma unroll
            for (int o = 16; o; o >>= 1) {
                #pragma unroll
                for (int rr = 0; rr < 4; rr++)
                    rd[rr] += __shfl_xor_sync(0xffffffffu, rd[rr], o);
            }
            if (lane == 0) {
                #pragma unroll
                for (int rr = 0; rr < 4; rr++) rowpart[g4 * 4 + rr][warp] = rd[rr];
            }
        }

        if (act) {
            float* cp = &g_colpartS[slot][i][b][c0];
            *(float4*)cp       = make_float4(colacc[0], colacc[1], colacc[2], colacc[3]);
            *(float4*)(cp + 4) = make_float4(colacc[4], colacc[5], colacc[6], colacc[7]);
        }

        __syncthreads();
        if (tid < RBS) {
            float tot = 0.f;
            #pragma unroll
            for (int w = 0; w < 8; w++) tot += rowpart[tid][w];
            g_symrow[slot][b * NN + start + tid] = tot;
        }
    }
}

// ---------------- sym finalize: S[r] = rowsum(r) + sum_{j<blk(r)} colpartS[j][r] ----------------
// grid (BB*NN/256, 2); blockIdx.y = slot
__global__ void sym_fin(const float* __restrict__ a, const float* __restrict__ bm,
                        int par, int mode)
{
    const int slot = blockIdx.y;
    const int i = blockIdx.x * 256 + threadIdx.x;       // i = b*NN + r
    const int b = i >> 11, r = i & (NN - 1);
    const int blk = r >> 4;                             // RBS = 16

    const float* cp = &g_colpartS[slot][0][b][r];
    const size_t stride = (size_t)BB * NN;
    float T0 = 0.f, T1 = 0.f, T2 = 0.f, T3 = 0.f;
    int j = 0;
    for (; j + 4 <= blk; j += 4) {
        T0 += cp[(size_t)j * stride];
        T1 += cp[(size_t)(j + 1) * stride];
        T2 += cp[(size_t)(j + 2) * stride];
        T3 += cp[(size_t)(j + 3) * stride];
    }
    for (; j < blk; j++) T0 += cp[(size_t)j * stride];
    float T = g_symrow[slot][i] + ((T0 + T1) + (T2 + T3));

    const float* meas = slot ? bm : a;
    if (mode == 0) {
        float pn = 0.5f * (g_pot[2 + slot][i] - logf(T));
        g_pot[2 + slot][i] = pn;
        g_wsym[par ^ 1][slot][i] = meas[i] * __expf(pn);
    } else {
        g_c[2 + slot][i] = -meas[i] * logf(T);
    }
}

// ---------------- final scalar ----------------
__global__ void final_reduce(float* __restrict__ out)
{
    const int tid = threadIdx.x;
    float s = 0.f;
    for (int i = tid; i < BB * NN; i += 1024)
        s += (g_c[0][i] + g_c[1][i]) - (g_c[2][i] + g_c[3][i]);
    #pragma unroll
    for (int o = 16; o; o >>= 1) s += __shfl_xor_sync(0xffffffffu, s, o);
    __shared__ float sm[32];
    if ((tid & 31) == 0) sm[tid >> 5] = s;
    __syncthreads();
    if (tid < 32) {
        float v = sm[tid];
        #pragma unroll
        for (int o = 16; o; o >>= 1) v += __shfl_xor_sync(0xffffffffu, v, o);
        if (tid == 0) out[0] = v / (float)BB;
    }
}

// ---------------- launcher ----------------
extern "C" void kernel_launch(void* const* d_in, const int* in_sizes, int n_in,
                              void* d_out, int out_size)
{
    const float* x  = (const float*)d_in[0];
    const float* a  = (const float*)d_in[1];
    const float* y  = (const float*)d_in[2];
    const float* bm = (const float*)d_in[3];
    float* out = (float*)d_out;

    shift_kernel<<<dim3(16, BB), 128>>>(x, y);
    init_kernel<<<(BB * NN + 255) / 256, 256>>>(a, bm);

    dim3 bg(16, 16, BB);
    dim3 xg(NRB, BB);
    dim3 smg(NRB / 2, BB, 2);
    dim3 sfg(BB * NN / 256, 2);

    // ---- xy phase ----
    build_xy<<<bg, 256>>>(x, y);
    for (int it = 0; it < 10; it++) {
        xy_main<<<xg, 256>>>(a, it & 1, 0);
        xy_fin<<<BB * NN / 256, 256>>>(bm, 0);
    }
    xy_main<<<xg, 256>>>(a, 0, 1);           // c0 + final colparts (wap parity 0)
    xy_fin<<<BB * NN / 256, 256>>>(bm, 1);   // c1

    // ---- merged symmetric phases (upper triangles only) ----
    build_xx<<<bg, 256>>>(x);
    build_yy<<<bg, 256>>>(y);
    for (int it = 0; it < 10; it++) {
        sym_main<<<smg, 256>>>(it & 1);
        sym_fin<<<sfg, 256>>>(a, bm, it & 1, 0);
    }
    sym_main<<<smg, 256>>>(0);               // final weights at parity 0
    sym_fin<<<sfg, 256>>>(a, bm, 0, 1);      // c2, c3

    final_reduce<<<1, 1024>>>(out);
}

// round 10
// speedup vs baseline: 2.3293x; 1.1723x over previous
#include <cuda_runtime.h>
#include <cuda_fp16.h>
#include <cuda_bf16.h>
#include <math.h>
#include <stdint.h>

#define BB 8
#define NN 2048
#define DD 32
#define XRBS 32                     // rows per xy_main block
#define XNRB (NN / XRBS)            // 64
#define RBS 16                      // rows per sym row-block
#define NRB (NN / RBS)              // 128

// ---------------- scratch (device globals; no allocations) ----------------
__device__ __nv_bfloat16 g_Exy[(size_t)BB * NN * NN]; // exp((sh_l - dist(x_l,y_k))/2), bf16
__device__ __half g_Exx[(size_t)BB * NN * NN];        // exp(-dist/2), fp16 (upper tiles valid)
__device__ __half g_Eyy[(size_t)BB * NN * NN];
__device__ float g_shift[BB * NN];
__device__ float g_pot[4][BB * NN];              // 0:f 1:g 2:fx 3:fy
__device__ float g_wg[BB * NN];                  // b * exp(g)
__device__ float g_wap[2][BB * NN];              // a * exp(f - sh/2), parity buffered
__device__ float g_wsym[2][2][BB * NN];          // [parity][0:xx,1:yy]
__device__ float g_colpart[XNRB][BB][NN];        // xy column partial sums
__device__ float g_colpartS[2][NRB][BB][NN];     // sym column partials per slot
__device__ float g_symrow[2][BB * NN];           // sym row sums (cols >= start part)
__device__ float g_c[4][BB * NN];                // eval contributions

// ---------------- small helpers ----------------
__device__ __forceinline__ uint32_t f2tf32(float f) {
    uint32_t r;
    asm("cvt.rna.tf32.f32 %0, %1;" : "=r"(r) : "f"(f));
    return r;
}
__device__ __forceinline__ void mma_tf32(float d[4],
    uint32_t a0, uint32_t a1, uint32_t a2, uint32_t a3, uint32_t b0, uint32_t b1)
{
    asm("mma.sync.aligned.m16n8k8.row.col.f32.tf32.tf32.f32 "
        "{%0,%1,%2,%3}, {%4,%5,%6,%7}, {%8,%9}, {%0,%1,%2,%3};"
        : "+f"(d[0]), "+f"(d[1]), "+f"(d[2]), "+f"(d[3])
        : "r"(a0), "r"(a1), "r"(a2), "r"(a3), "r"(b0), "r"(b1));
}

// ---------------- row shifts ----------------
__global__ void shift_kernel(const float* __restrict__ x, const float* __restrict__ y)
{
    const int b = blockIdx.y;
    const int l = blockIdx.x * 128 + threadIdx.x;
    const float* Pb = x + (size_t)b * NN * DD;
    const float* Qb = y + (size_t)b * NN * DD;

    __shared__ float sq[128][DD + 1];
    for (int i = threadIdx.x; i < 128 * DD; i += 128)
        sq[i >> 5][i & 31] = Qb[i];
    __syncthreads();

    float p[DD];
    #pragma unroll
    for (int d = 0; d < DD; d++) p[d] = Pb[(size_t)l * DD + d];

    float mn = 3.4e38f;
    for (int k = 0; k < 128; k++) {
        float acc = 0.f;
        #pragma unroll
        for (int d = 0; d < DD; d++) {
            float df = p[d] - sq[k][d];
            acc = fmaf(df, df, acc);
        }
        mn = fminf(mn, acc);
    }
    g_shift[b * NN + l] = mn;
}

// ---------------- init ----------------
__global__ void init_kernel(const float* __restrict__ a, const float* __restrict__ bm)
{
    int i = blockIdx.x * 256 + threadIdx.x;
    if (i < BB * NN) {
        g_pot[0][i] = 0.f; g_pot[1][i] = 0.f;
        g_pot[2][i] = 0.f; g_pot[3][i] = 0.f;
        g_wg[i] = bm[i];
        g_wap[0][i] = a[i] * __expf(-0.5f * g_shift[i]);
        g_wsym[0][0][i] = a[i];
        g_wsym[0][1][i] = bm[i];
    }
}

// ---------------- tensor-core build core (tf32 3-product split) ----------------
template <int USE_SHIFT, int OUT>
__device__ __forceinline__ void build_core(const float* __restrict__ P,
                                           const float* __restrict__ Q)
{
    __shared__ float sp[128][DD + 4];
    __shared__ float sq[128][DD + 4];
    __shared__ float snp[128], snq[128];

    const int b  = blockIdx.z;
    const int l0 = blockIdx.y * 128;
    const int k0 = blockIdx.x * 128;
    const int tid = threadIdx.x;
    const float* Pb = P + (size_t)b * NN * DD;
    const float* Qb = Q + (size_t)b * NN * DD;

    for (int i = tid; i < 128 * DD; i += 256) {
        int r = i >> 5, d = i & 31;
        sp[r][d] = Pb[(size_t)(l0 + r) * DD + d];
        sq[r][d] = Qb[(size_t)(k0 + r) * DD + d];
    }
    __syncthreads();

    if (tid < 128) {
        float s = 0.f;
        #pragma unroll
        for (int d = 0; d < DD; d++) s = fmaf(sp[tid][d], sp[tid][d], s);
        snp[tid] = s;
    } else {
        int r = tid - 128;
        float s = 0.f;
        #pragma unroll
        for (int d = 0; d < DD; d++) s = fmaf(sq[r][d], sq[r][d], s);
        snq[r] = s;
    }
    __syncthreads();

    const int warp = tid >> 5, lane = tid & 31;
    const int g = lane >> 2, tg = lane & 3;
    const int nb = warp * 16;

    float acc[8][2][4];
    #pragma unroll
    for (int r = 0; r < 8; r++)
        #pragma unroll
        for (int c = 0; c < 2; c++)
            #pragma unroll
            for (int q = 0; q < 4; q++) acc[r][c][q] = 0.f;

    #pragma unroll
    for (int kt = 0; kt < 4; kt++) {
        const int kc = kt * 8;
        uint32_t bh[2][2], bl[2][2];
        #pragma unroll
        for (int c = 0; c < 2; c++) {
            float f0 = sq[nb + c * 8 + g][kc + tg];
            float f1 = sq[nb + c * 8 + g][kc + tg + 4];
            bh[c][0] = f2tf32(f0); bl[c][0] = f2tf32(f0 - __uint_as_float(bh[c][0]));
            bh[c][1] = f2tf32(f1); bl[c][1] = f2tf32(f1 - __uint_as_float(bh[c][1]));
        }
        #pragma unroll
        for (int r = 0; r < 8; r++) {
            float a00 = sp[r * 16 + g][kc + tg];
            float a10 = sp[r * 16 + g + 8][kc + tg];
            float a01 = sp[r * 16 + g][kc + tg + 4];
            float a11 = sp[r * 16 + g + 8][kc + tg + 4];
            uint32_t h0 = f2tf32(a00), h1 = f2tf32(a10), h2 = f2tf32(a01), h3 = f2tf32(a11);
            uint32_t l0r = f2tf32(a00 - __uint_as_float(h0));
            uint32_t l1r = f2tf32(a10 - __uint_as_float(h1));
            uint32_t l2r = f2tf32(a01 - __uint_as_float(h2));
            uint32_t l3r = f2tf32(a11 - __uint_as_float(h3));
            #pragma unroll
            for (int c = 0; c < 2; c++) {
                mma_tf32(acc[r][c], h0, h1, h2, h3, bh[c][0], bh[c][1]);
                mma_tf32(acc[r][c], h0, h1, h2, h3, bl[c][0], bl[c][1]);
                mma_tf32(acc[r][c], l0r, l1r, l2r, l3r, bh[c][0], bh[c][1]);
            }
        }
    }

    const size_t base = (size_t)b * NN * NN;
    #pragma unroll
    for (int r = 0; r < 8; r++) {
        const int row0 = l0 + r * 16 + g;
        const int row1 = row0 + 8;
        const float nx0 = snp[r * 16 + g], nx1 = snp[r * 16 + g + 8];
        const float sh0 = USE_SHIFT ? g_shift[b * NN + row0] : 0.f;
        const float sh1 = USE_SHIFT ? g_shift[b * NN + row1] : 0.f;
        #pragma unroll
        for (int c = 0; c < 2; c++) {
            const int col = k0 + nb + c * 8 + tg * 2;
            const float ny0 = snq[nb + c * 8 + tg * 2];
            const float ny1 = snq[nb + c * 8 + tg * 2 + 1];
            float e00 = __expf(0.5f * (sh0 - fmaxf(nx0 + ny0 - 2.f * acc[r][c][0], 0.f)));
            float e01 = __expf(0.5f * (sh0 - fmaxf(nx0 + ny1 - 2.f * acc[r][c][1], 0.f)));
            float e10 = __expf(0.5f * (sh1 - fmaxf(nx1 + ny0 - 2.f * acc[r][c][2], 0.f)));
            float e11 = __expf(0.5f * (sh1 - fmaxf(nx1 + ny1 - 2.f * acc[r][c][3], 0.f)));
            if (OUT == 0) {
                *(__nv_bfloat162*)&g_Exy[base + (size_t)row0 * NN + col] =
                    __floats2bfloat162_rn(e00, e01);
                *(__nv_bfloat162*)&g_Exy[base + (size_t)row1 * NN + col] =
                    __floats2bfloat162_rn(e10, e11);
            } else {
                __half* M = (OUT == 1) ? g_Exx : g_Eyy;
                *(__half2*)&M[base + (size_t)row0 * NN + col] = __floats2half2_rn(e00, e01);
                *(__half2*)&M[base + (size_t)row1 * NN + col] = __floats2half2_rn(e10, e11);
            }
        }
    }
}

__global__ void __launch_bounds__(256) build_xy(const float* __restrict__ x,
                                                const float* __restrict__ y)
{ build_core<1, 0>(x, y); }
__global__ void __launch_bounds__(256) build_xx(const float* __restrict__ x)
{ if (blockIdx.x < blockIdx.y) return; build_core<0, 1>(x, x); }
__global__ void __launch_bounds__(256) build_yy(const float* __restrict__ y)
{ if (blockIdx.x < blockIdx.y) return; build_core<0, 2>(y, y); }

// ---------------- row-batch compute helpers (8 rows) ----------------
__device__ __forceinline__ void rows8_bf16(const uint4 m[8], const float* swap8,
                                           const float4& wg0, const float4& wg1,
                                           float rd[8], float colacc[8])
{
    #pragma unroll
    for (int rr = 0; rr < 8; rr++) {
        float2 e0 = __bfloat1622float2(*reinterpret_cast<const __nv_bfloat162*>(&m[rr].x));
        float2 e1 = __bfloat1622float2(*reinterpret_cast<const __nv_bfloat162*>(&m[rr].y));
        float2 e2 = __bfloat1622float2(*reinterpret_cast<const __nv_bfloat162*>(&m[rr].z));
        float2 e3 = __bfloat1622float2(*reinterpret_cast<const __nv_bfloat162*>(&m[rr].w));
        float wr = swap8[rr];
        float s = 0.f;
        s = fmaf(e0.x, wg0.x, s); s = fmaf(e0.y, wg0.y, s);
        s = fmaf(e1.x, wg0.z, s); s = fmaf(e1.y, wg0.w, s);
        s = fmaf(e2.x, wg1.x, s); s = fmaf(e2.y, wg1.y, s);
        s = fmaf(e3.x, wg1.z, s); s = fmaf(e3.y, wg1.w, s);
        rd[rr] = s;
        colacc[0] = fmaf(e0.x, wr, colacc[0]); colacc[1] = fmaf(e0.y, wr, colacc[1]);
        colacc[2] = fmaf(e1.x, wr, colacc[2]); colacc[3] = fmaf(e1.y, wr, colacc[3]);
        colacc[4] = fmaf(e2.x, wr, colacc[4]); colacc[5] = fmaf(e2.y, wr, colacc[5]);
        colacc[6] = fmaf(e3.x, wr, colacc[6]); colacc[7] = fmaf(e3.y, wr, colacc[7]);
    }
}

__device__ __forceinline__ void rows8_fp16(const uint4 m[8], const float* swap8,
                                           const float4& wg0, const float4& wg1,
                                           float rd[8], float colacc[8])
{
    #pragma unroll
    for (int rr = 0; rr < 8; rr++) {
        float2 e0 = __half22float2(*reinterpret_cast<const __half2*>(&m[rr].x));
        float2 e1 = __half22float2(*reinterpret_cast<const __half2*>(&m[rr].y));
        float2 e2 = __half22float2(*reinterpret_cast<const __half2*>(&m[rr].z));
        float2 e3 = __half22float2(*reinterpret_cast<const __half2*>(&m[rr].w));
        float wr = swap8[rr];
        float s = 0.f;
        s = fmaf(e0.x, wg0.x, s); s = fmaf(e0.y, wg0.y, s);
        s = fmaf(e1.x, wg0.z, s); s = fmaf(e1.y, wg0.w, s);
        s = fmaf(e2.x, wg1.x, s); s = fmaf(e2.y, wg1.y, s);
        s = fmaf(e3.x, wg1.z, s); s = fmaf(e3.y, wg1.w, s);
        rd[rr] = s;
        colacc[0] = fmaf(e0.x, wr, colacc[0]); colacc[1] = fmaf(e0.y, wr, colacc[1]);
        colacc[2] = fmaf(e1.x, wr, colacc[2]); colacc[3] = fmaf(e1.y, wr, colacc[3]);
        colacc[4] = fmaf(e2.x, wr, colacc[4]); colacc[5] = fmaf(e2.y, wr, colacc[5]);
        colacc[6] = fmaf(e3.x, wr, colacc[6]); colacc[7] = fmaf(e3.y, wr, colacc[7]);
    }
}

// ---------------- xy main pass: row sums + column partials, 8-deep MLP ----------------
__global__ void __launch_bounds__(256) xy_main(const float* __restrict__ a, int par, int mode)
{
    const int b = blockIdx.y, rb = blockIdx.x;
    const int tid = threadIdx.x, warp = tid >> 5, lane = tid & 31;
    const int c0 = warp * 256 + lane * 8;

    __shared__ float swap_s[XRBS];
    __shared__ float rowpart[XRBS][9];

    if (tid < XRBS) swap_s[tid] = g_wap[par][b * NN + rb * XRBS + tid];

    const float4 wg0 = *(const float4*)&g_wg[b * NN + c0];
    const float4 wg1 = *(const float4*)&g_wg[b * NN + c0 + 4];
    __syncthreads();

    const __nv_bfloat16* Srow = g_Exy + ((size_t)b * NN + rb * XRBS) * NN + c0;

    float colacc[8];
    #pragma unroll
    for (int j = 0; j < 8; j++) colacc[j] = 0.f;

    for (int g8 = 0; g8 < XRBS / 8; g8++) {
        uint4 m[8];
        #pragma unroll
        for (int rr = 0; rr < 8; rr++)
            m[rr] = __ldg((const uint4*)(Srow + (size_t)(g8 * 8 + rr) * NN));

        float rd[8];
        rows8_bf16(m, &swap_s[g8 * 8], wg0, wg1, rd, colacc);

        #pragma unroll
        for (int o = 16; o; o >>= 1) {
            #pragma unroll
            for (int rr = 0; rr < 8; rr++)
                rd[rr] += __shfl_xor_sync(0xffffffffu, rd[rr], o);
        }
        if (lane == 0) {
            #pragma unroll
            for (int rr = 0; rr < 8; rr++) rowpart[g8 * 8 + rr][warp] = rd[rr];
        }
    }

    float* cp = &g_colpart[rb][b][c0];
    *(float4*)cp       = make_float4(colacc[0], colacc[1], colacc[2], colacc[3]);
    *(float4*)(cp + 4) = make_float4(colacc[4], colacc[5], colacc[6], colacc[7]);

    __syncthreads();

    if (tid < XRBS) {
        const int row = rb * XRBS + tid;
        const int idx = b * NN + row;
        float tot = 0.f;
        #pragma unroll
        for (int w = 0; w < 8; w++) tot += rowpart[tid][w];
        const float sh = g_shift[idx];
        if (mode == 0) {
            float fn = 0.5f * (g_pot[0][idx] - logf(tot) + 0.5f * sh);
            g_pot[0][idx] = fn;
            g_wap[par ^ 1][idx] = a[idx] * __expf(fn - 0.5f * sh);
        } else {
            g_c[0][idx] = a[idx] * (0.5f * sh - logf(tot));
        }
    }
}

// ---------------- xy finalize ----------------
__global__ void xy_fin(const float* __restrict__ bm, int mode)
{
    const int i = blockIdx.x * 256 + threadIdx.x;       // i = b*NN + k
    const int b = i >> 11, k = i & (NN - 1);
    float T = 0.f;
    #pragma unroll 8
    for (int rb = 0; rb < XNRB; rb++) T += g_colpart[rb][b][k];
    if (mode == 0) {
        float gn = 0.5f * (g_pot[1][i] - logf(T));
        g_pot[1][i] = gn;
        g_wg[i] = bm[i] * __expf(gn);
    } else {
        g_c[1][i] = -bm[i] * logf(T);
    }
}

// ---------------- sym main pass (SYMV, upper triangle) ----------------
// grid (NRB/2, BB, 2). Block bx handles row-blocks {bx, NRB-1-bx}, cols >= 16*i each.
// wact (warp-uniform) gates compute+shuffles; lact (per-lane) only predicates load/store.
__global__ void __launch_bounds__(256) sym_main(int par)
{
    const int slot = blockIdx.z, b = blockIdx.y, bx = blockIdx.x;
    const int tid = threadIdx.x, warp = tid >> 5, lane = tid & 31;
    const int c0 = warp * 256 + lane * 8;
    const __half* M = slot ? g_Eyy : g_Exx;
    const float* wv = g_wsym[par][slot] + b * NN;

    __shared__ float swap_s[RBS];
    __shared__ float rowpart[RBS][9];

    const float4 w0 = *(const float4*)&wv[c0];
    const float4 w1 = *(const float4*)&wv[c0 + 4];

    #pragma unroll
    for (int s = 0; s < 2; s++) {
        const int i = s ? (NRB - 1 - bx) : bx;
        const int start = i * RBS;
        const bool wact = (warp * 256 + 256) > start;   // warp-uniform
        const bool lact = c0 >= start;                  // per-lane

        __syncthreads();
        if (tid < RBS) swap_s[tid] = wv[start + tid];
        __syncthreads();

        if (wact) {
            const __half* Srow = M + ((size_t)b * NN + start) * NN + c0;
            float colacc[8];
            #pragma unroll
            for (int j = 0; j < 8; j++) colacc[j] = 0.f;

            #pragma unroll
            for (int g8 = 0; g8 < RBS / 8; g8++) {
                uint4 m[8];
                #pragma unroll
                for (int rr = 0; rr < 8; rr++)
                    m[rr] = lact ? __ldg((const uint4*)(Srow + (size_t)(g8 * 8 + rr) * NN))
                                 : make_uint4(0u, 0u, 0u, 0u);

                float rd[8];
                rows8_fp16(m, &swap_s[g8 * 8], w0, w1, rd, colacc);

                #pragma unroll
                for (int o = 16; o; o >>= 1) {
                    #pragma unroll
                    for (int rr = 0; rr < 8; rr++)
                        rd[rr] += __shfl_xor_sync(0xffffffffu, rd[rr], o);
                }
                if (lane == 0) {
                    #pragma unroll
                    for (int rr = 0; rr < 8; rr++) rowpart[g8 * 8 + rr][warp] = rd[rr];
                }
            }

            if (lact) {
                float* cp = &g_colpartS[slot][i][b][c0];
                *(float4*)cp       = make_float4(colacc[0], colacc[1], colacc[2], colacc[3]);
                *(float4*)(cp + 4) = make_float4(colacc[4], colacc[5], colacc[6], colacc[7]);
            }
        } else if (lane == 0) {
            #pragma unroll
            for (int r = 0; r < RBS; r++) rowpart[r][warp] = 0.f;
        }

        __syncthreads();
        if (tid < RBS) {
            float tot = 0.f;
            #pragma unroll
            for (int w = 0; w < 8; w++) tot += rowpart[tid][w];
            g_symrow[slot][b * NN + start + tid] = tot;
        }
    }
}

// ---------------- sym finalize: S[r] = rowsum(r) + sum_{j<blk(r)} colpartS[j][r] ----------------
__global__ void sym_fin(const float* __restrict__ a, const float* __restrict__ bm,
                        int par, int mode)
{
    const int slot = blockIdx.y;
    const int i = blockIdx.x * 256 + threadIdx.x;       // i = b*NN + r
    const int b = i >> 11, r = i & (NN - 1);
    const int blk = r >> 4;                             // RBS = 16

    const float* cp = &g_colpartS[slot][0][b][r];
    const size_t stride = (size_t)BB * NN;
    float T0 = 0.f, T1 = 0.f, T2 = 0.f, T3 = 0.f;
    int j = 0;
    for (; j + 4 <= blk; j += 4) {
        T0 += cp[(size_t)j * stride];
        T1 += cp[(size_t)(j + 1) * stride];
        T2 += cp[(size_t)(j + 2) * stride];
        T3 += cp[(size_t)(j + 3) * stride];
    }
    for (; j < blk; j++) T0 += cp[(size_t)j * stride];
    float T = g_symrow[slot][i] + ((T0 + T1) + (T2 + T3));

    const float* meas = slot ? bm : a;
    if (mode == 0) {
        float pn = 0.5f * (g_pot[2 + slot][i] - logf(T));
        g_pot[2 + slot][i] = pn;
        g_wsym[par ^ 1][slot][i] = meas[i] * __expf(pn);
    } else {
        g_c[2 + slot][i] = -meas[i] * logf(T);
    }
}

// ---------------- final scalar ----------------
__global__ void final_reduce(float* __restrict__ out)
{
    const int tid = threadIdx.x;
    float s = 0.f;
    for (int i = tid; i < BB * NN; i += 1024)
        s += (g_c[0][i] + g_c[1][i]) - (g_c[2][i] + g_c[3][i]);
    #pragma unroll
    for (int o = 16; o; o >>= 1) s += __shfl_xor_sync(0xffffffffu, s, o);
    __shared__ float sm[32];
    if ((tid & 31) == 0) sm[tid >> 5] = s;
    __syncthreads();
    if (tid < 32) {
        float v = sm[tid];
        #pragma unroll
        for (int o = 16; o; o >>= 1) v += __shfl_xor_sync(0xffffffffu, v, o);
        if (tid == 0) out[0] = v / (float)BB;
    }
}

// ---------------- launcher ----------------
extern "C" void kernel_launch(void* const* d_in, const int* in_sizes, int n_in,
                              void* d_out, int out_size)
{
    const float* x  = (const float*)d_in[0];
    const float* a  = (const float*)d_in[1];
    const float* y  = (const float*)d_in[2];
    const float* bm = (const float*)d_in[3];
    float* out = (float*)d_out;

    shift_kernel<<<dim3(16, BB), 128>>>(x, y);
    init_kernel<<<(BB * NN + 255) / 256, 256>>>(a, bm);

    dim3 bg(16, 16, BB);
    dim3 xg(XNRB, BB);
    dim3 smg(NRB / 2, BB, 2);
    dim3 sfg(BB * NN / 256, 2);

    // ---- xy phase ----
    build_xy<<<bg, 256>>>(x, y);
    for (int it = 0; it < 10; it++) {
        xy_main<<<xg, 256>>>(a, it & 1, 0);
        xy_fin<<<BB * NN / 256, 256>>>(bm, 0);
    }
    xy_main<<<xg, 256>>>(a, 0, 1);           // c0 + final colparts (wap parity 0)
    xy_fin<<<BB * NN / 256, 256>>>(bm, 1);   // c1

    // ---- merged symmetric phases (upper triangles only) ----
    build_xx<<<bg, 256>>>(x);
    build_yy<<<bg, 256>>>(y);
    for (int it = 0; it < 10; it++) {
        sym_main<<<smg, 256>>>(it & 1);
        sym_fin<<<sfg, 256>>>(a, bm, it & 1, 0);
    }
    sym_main<<<smg, 256>>>(0);               // final weights at parity 0
    sym_fin<<<sfg, 256>>>(a, bm, 0, 1);      // c2, c3

    final_reduce<<<1, 1024>>>(out);
}